// round 1
// baseline (speedup 1.0000x reference)
#include <cuda_runtime.h>
#include <cstdio>

// ---------------- problem constants ----------------
#define DIMD   256
#define HEADS  8
#define HD     32
#define DEPTH  2
#define DFF    128
#define TT     64
#define NN     2048
#define SS     256
#define LL     8
#define NSEQ_S (TT*SS)          // 16384 spatial sequences
#define SQ_S   (1+LL)           // 9 tokens per spatial seq
#define NTOK_S (NSEQ_S*SQ_S)    // 147456
#define NSEQ_T SS               // 256 temporal sequences
#define SQ_T   TT               // 64
#define NTOK_T (NSEQ_T*SQ_T)    // 16384

// ---------------- scratch (static device memory; no allocations) ----------------
__device__ float g_x   [(size_t)NTOK_S * DIMD];     // activations
__device__ float g_qkv [(size_t)NTOK_S * 3 * DIMD]; // qkv projections
__device__ float g_attn[(size_t)NTOK_S * DIMD];     // attention concat output
__device__ float g_tmp [(size_t)NTOK_S * DIMD];     // proj / ffn output
__device__ float g_h   [(size_t)NTOK_S * DFF];      // ffn hidden

// ---------------- embed: gelu(moveinfo @ w_in^T + b_in), build [T*S, 9, D] with cls ----------------
__global__ void embed_kernel(const float* __restrict__ mi, const int* __restrict__ sse,
                             const float* __restrict__ w_in, const float* __restrict__ b_in,
                             float* __restrict__ x)
{
    size_t gid = (size_t)blockIdx.x * 256 + threadIdx.x;   // NTOK_S * 256 total
    int d   = (int)(gid & 255);
    int tok = (int)(gid >> 8);
    int r   = tok % SQ_S;
    int seq = tok / SQ_S;          // = t*SS + s
    int s   = seq & (SS - 1);
    int t   = seq >> 8;            // SS = 256
    float val;
    if (r == 0) {
        val = 1e-5f;
    } else {
        int n = sse[2 * s] + (r - 1);
        const float* mp = mi + ((size_t)n * TT + t) * 2;
        float z = mp[0] * w_in[d * 2 + 0] + mp[1] * w_in[d * 2 + 1] + b_in[d];
        val = 0.5f * z * (1.0f + erff(z * 0.70710678118654752f));
    }
    x[gid] = val;
}

// ---------------- generic NT GEMM: C[M,N] = act(A[M,K] @ W[N,K]^T + bias[N]) ----------------
// BM=64, BN=64, BK=16, 256 threads, 4x4 micro-tiles. Requires M%64==0, N%64==0, K%16==0.
#define BM 64
#define BN 64
#define BK 16

__global__ void gemm_nt(const float* __restrict__ A, const float* __restrict__ W,
                        const float* __restrict__ bias, float* __restrict__ C,
                        int M, int N, int K, int relu)
{
    __shared__ __align__(16) float As[BK][BM + 4];
    __shared__ __align__(16) float Bs[BK][BN + 4];

    const int tid = threadIdx.x;
    const int tx = tid & 15;      // 0..15 -> N micro
    const int ty = tid >> 4;      // 0..15 -> M micro
    const int m0 = blockIdx.y * BM;
    const int n0 = blockIdx.x * BN;

    const int lr = tid >> 2;          // 0..63 tile row
    const int lc = (tid & 3) * 4;     // 0,4,8,12 tile k

    float acc[4][4] = {};

    for (int k0 = 0; k0 < K; k0 += BK) {
        float4 av = *(const float4*)(A + (size_t)(m0 + lr) * K + k0 + lc);
        float4 bv = *(const float4*)(W + (size_t)(n0 + lr) * K + k0 + lc);
        As[lc + 0][lr] = av.x; As[lc + 1][lr] = av.y; As[lc + 2][lr] = av.z; As[lc + 3][lr] = av.w;
        Bs[lc + 0][lr] = bv.x; Bs[lc + 1][lr] = bv.y; Bs[lc + 2][lr] = bv.z; Bs[lc + 3][lr] = bv.w;
        __syncthreads();
        #pragma unroll
        for (int k = 0; k < BK; k++) {
            float4 a = *(const float4*)&As[k][ty * 4];
            float4 b = *(const float4*)&Bs[k][tx * 4];
            acc[0][0] += a.x * b.x; acc[0][1] += a.x * b.y; acc[0][2] += a.x * b.z; acc[0][3] += a.x * b.w;
            acc[1][0] += a.y * b.x; acc[1][1] += a.y * b.y; acc[1][2] += a.y * b.z; acc[1][3] += a.y * b.w;
            acc[2][0] += a.z * b.x; acc[2][1] += a.z * b.y; acc[2][2] += a.z * b.z; acc[2][3] += a.z * b.w;
            acc[3][0] += a.w * b.x; acc[3][1] += a.w * b.y; acc[3][2] += a.w * b.z; acc[3][3] += a.w * b.w;
        }
        __syncthreads();
    }

    float4 bb = *(const float4*)(bias + n0 + tx * 4);
    #pragma unroll
    for (int i = 0; i < 4; i++) {
        int r = m0 + ty * 4 + i;
        float4 v;
        v.x = acc[i][0] + bb.x;
        v.y = acc[i][1] + bb.y;
        v.z = acc[i][2] + bb.z;
        v.w = acc[i][3] + bb.w;
        if (relu) {
            v.x = fmaxf(v.x, 0.f); v.y = fmaxf(v.y, 0.f);
            v.z = fmaxf(v.z, 0.f); v.w = fmaxf(v.w, 0.f);
        }
        *(float4*)(C + (size_t)r * N + n0 + tx * 4) = v;
    }
}

// ---------------- attention: per (sequence, head) block, Sq <= 64, HD = 32 ----------------
__global__ void attn_kernel(const float* __restrict__ qkv, float* __restrict__ out, int Sq)
{
    const int seq  = blockIdx.x;
    const int head = blockIdx.y;
    const int tid  = threadIdx.x;      // 128
    const int lane = tid & 31;
    const int w    = tid >> 5;

    __shared__ float Ks[64][33];
    __shared__ float Vs[64][33];
    __shared__ float qs[4][33];
    __shared__ float ps[4][64];

    const float* base = qkv + (size_t)seq * Sq * (3 * DIMD) + head * HD;

    for (int idx = tid; idx < Sq * HD; idx += 128) {
        int rr = idx >> 5, dd = idx & 31;
        Ks[rr][dd] = base[(size_t)rr * (3 * DIMD) + DIMD + dd];
        Vs[rr][dd] = base[(size_t)rr * (3 * DIMD) + 2 * DIMD + dd];
    }
    __syncthreads();

    const float scale = 0.17677669529663689f;  // 1/sqrt(32)

    for (int i = w; i < Sq; i += 4) {
        qs[w][lane] = base[(size_t)i * (3 * DIMD) + lane];
        __syncwarp();
        float sc0 = -1e30f, sc1 = -1e30f;
        if (lane < Sq) {
            float sacc = 0.f;
            #pragma unroll
            for (int dd = 0; dd < HD; dd++) sacc += qs[w][dd] * Ks[lane][dd];
            sc0 = sacc * scale;
        }
        int j1 = lane + 32;
        if (j1 < Sq) {
            float sacc = 0.f;
            #pragma unroll
            for (int dd = 0; dd < HD; dd++) sacc += qs[w][dd] * Ks[j1][dd];
            sc1 = sacc * scale;
        }
        float mx = fmaxf(sc0, sc1);
        #pragma unroll
        for (int o = 16; o; o >>= 1) mx = fmaxf(mx, __shfl_xor_sync(0xffffffffu, mx, o));
        float e0 = (lane < Sq) ? expf(sc0 - mx) : 0.f;
        float e1 = (j1 < Sq) ? expf(sc1 - mx) : 0.f;
        float se = e0 + e1;
        #pragma unroll
        for (int o = 16; o; o >>= 1) se += __shfl_xor_sync(0xffffffffu, se, o);
        float inv = 1.f / se;
        if (lane < Sq) ps[w][lane] = e0 * inv;
        if (j1 < Sq)   ps[w][j1]   = e1 * inv;
        __syncwarp();
        float acc = 0.f;
        for (int j = 0; j < Sq; j++) acc += ps[w][j] * Vs[j][lane];
        out[((size_t)seq * Sq + i) * DIMD + head * HD + lane] = acc;
        __syncwarp();
    }
}

// ---------------- fused residual + LayerNorm: out = LN(X + H) * w + b ----------------
__global__ void add_ln_kernel(const float* __restrict__ X, const float* __restrict__ H,
                              const float* __restrict__ w, const float* __restrict__ b,
                              float* __restrict__ out)
{
    const int row = blockIdx.x;
    const int tid = threadIdx.x;   // 256 == DIMD
    float v = X[(size_t)row * DIMD + tid] + H[(size_t)row * DIMD + tid];
    float s = v, s2 = v * v;
    #pragma unroll
    for (int o = 16; o; o >>= 1) {
        s  += __shfl_xor_sync(0xffffffffu, s,  o);
        s2 += __shfl_xor_sync(0xffffffffu, s2, o);
    }
    __shared__ float ws[8], ws2[8];
    if ((tid & 31) == 0) { ws[tid >> 5] = s; ws2[tid >> 5] = s2; }
    __syncthreads();
    float ts = 0.f, ts2 = 0.f;
    #pragma unroll
    for (int i = 0; i < 8; i++) { ts += ws[i]; ts2 += ws2[i]; }
    float mean = ts * (1.0f / DIMD);
    float var  = ts2 * (1.0f / DIMD) - mean * mean;
    out[(size_t)row * DIMD + tid] = (v - mean) * rsqrtf(var + 1e-5f) * w[tid] + b[tid];
}

// ---------------- cls extraction: t_x[(s*T+t), d] = x[((t*S+s)*9 + 0), d] ----------------
__global__ void extract_cls_kernel(const float* __restrict__ x, float* __restrict__ tx)
{
    size_t gid = (size_t)blockIdx.x * 256 + threadIdx.x;   // NTOK_T * 256
    int d   = (int)(gid & 255);
    int tok = (int)(gid >> 8);      // s*T + t
    int t = tok & (TT - 1);
    int s = tok >> 6;               // TT = 64
    tx[gid] = x[(((size_t)t * SS + s) * SQ_S) * DIMD + d];
}

// ---------------- host orchestration ----------------
static inline void launch_gemm(const float* A, const float* W, const float* bias,
                               float* C, int M, int N, int K, int relu)
{
    dim3 grid(N / BN, M / BM);
    gemm_nt<<<grid, 256>>>(A, W, bias, C, M, N, K, relu);
}

struct LayerW {
    const float *qkvw, *qkvb, *ow, *ob, *l1w, *l1b, *l2w, *l2b, *ln1w, *ln1b, *ln2w, *ln2b;
};

static void run_layer(float* x, float* qkv, float* attnb, float* tmp, float* h,
                      const LayerW& L, int nseq, int Sq, float* final_out)
{
    const int ntok = nseq * Sq;
    launch_gemm(x, L.qkvw, L.qkvb, qkv, ntok, 3 * DIMD, DIMD, 0);
    attn_kernel<<<dim3(nseq, HEADS), 128>>>(qkv, attnb, Sq);
    launch_gemm(attnb, L.ow, L.ob, tmp, ntok, DIMD, DIMD, 0);
    add_ln_kernel<<<ntok, DIMD>>>(x, tmp, L.ln1w, L.ln1b, x);
    launch_gemm(x, L.l1w, L.l1b, h, ntok, DFF, DIMD, 1);
    launch_gemm(h, L.l2w, L.l2b, tmp, ntok, DIMD, DFF, 0);
    add_ln_kernel<<<ntok, DIMD>>>(x, tmp, L.ln2w, L.ln2b, final_out ? final_out : x);
}

static LayerW make_layer(const float* const* p, int l)
{
    LayerW L;
    L.qkvw = p[0]  + (size_t)l * 3 * DIMD * DIMD;
    L.qkvb = p[1]  + (size_t)l * 3 * DIMD;
    L.ow   = p[2]  + (size_t)l * DIMD * DIMD;
    L.ob   = p[3]  + (size_t)l * DIMD;
    L.l1w  = p[4]  + (size_t)l * DFF * DIMD;
    L.l1b  = p[5]  + (size_t)l * DFF;
    L.l2w  = p[6]  + (size_t)l * DIMD * DFF;
    L.l2b  = p[7]  + (size_t)l * DIMD;
    L.ln1w = p[8]  + (size_t)l * DIMD;
    L.ln1b = p[9]  + (size_t)l * DIMD;
    L.ln2w = p[10] + (size_t)l * DIMD;
    L.ln2b = p[11] + (size_t)l * DIMD;
    return L;
}

extern "C" void kernel_launch(void* const* d_in, const int* in_sizes, int n_in,
                              void* d_out, int out_size)
{
    const float* moveinfo = (const float*)d_in[0];
    const int*   sse      = (const int*)  d_in[1];
    const float* w_in     = (const float*)d_in[2];
    const float* b_in     = (const float*)d_in[3];
    const float* sp[12];
    const float* tp[12];
    for (int i = 0; i < 12; i++) sp[i] = (const float*)d_in[4 + i];
    for (int i = 0; i < 12; i++) tp[i] = (const float*)d_in[16 + i];

    float *x, *qkv, *attnb, *tmp, *h;
    cudaGetSymbolAddress((void**)&x,     g_x);
    cudaGetSymbolAddress((void**)&qkv,   g_qkv);
    cudaGetSymbolAddress((void**)&attnb, g_attn);
    cudaGetSymbolAddress((void**)&tmp,   g_tmp);
    cudaGetSymbolAddress((void**)&h,     g_h);

    // 1) input embedding + cls-token assembly: x = [T*S, 9, 256]
    embed_kernel<<<NTOK_S, 256>>>(moveinfo, sse, w_in, b_in, x);

    // 2) spatial encoder (2 layers), x in-place
    for (int l = 0; l < DEPTH; l++) {
        LayerW L = make_layer(sp, l);
        run_layer(x, qkv, attnb, tmp, h, L, NSEQ_S, SQ_S, nullptr);
    }

    // 3) cls extraction -> temporal input [S, T, 256] in tmp
    extract_cls_kernel<<<NTOK_T, 256>>>(x, tmp);

    // 4) temporal encoder (2 layers); reuse: x_t = tmp, attn-out = g_x, scratch = g_attn
    for (int l = 0; l < DEPTH; l++) {
        LayerW L = make_layer(tp, l);
        const int ntok = NTOK_T;
        launch_gemm(tmp, L.qkvw, L.qkvb, qkv, ntok, 3 * DIMD, DIMD, 0);
        attn_kernel<<<dim3(NSEQ_T, HEADS), 128>>>(qkv, x, SQ_T);
        launch_gemm(x, L.ow, L.ob, attnb, ntok, DIMD, DIMD, 0);
        add_ln_kernel<<<ntok, DIMD>>>(tmp, attnb, L.ln1w, L.ln1b, tmp);
        launch_gemm(tmp, L.l1w, L.l1b, h, ntok, DFF, DIMD, 1);
        launch_gemm(h, L.l2w, L.l2b, attnb, ntok, DIMD, DFF, 0);
        float* outp = (l == DEPTH - 1) ? (float*)d_out : tmp;
        add_ln_kernel<<<ntok, DIMD>>>(tmp, attnb, L.ln2w, L.ln2b, outp);
    }
}

// round 3
// speedup vs baseline: 1.7541x; 1.7541x over previous
#include <cuda_runtime.h>
#include <cuda_bf16.h>
#include <cstdint>

// ---------------- problem constants ----------------
#define DIMD   256
#define HEADS  8
#define HD     32
#define DEPTH  2
#define DFF    128
#define TT     64
#define SS     256
#define LL     8
#define NSEQ_S (TT*SS)          // 16384 spatial sequences
#define SQ_S   (1+LL)           // 9 tokens
#define NTOK_S (NSEQ_S*SQ_S)    // 147456
#define NSEQ_T SS
#define SQ_T   TT
#define NTOK_T (NSEQ_T*SQ_T)    // 16384

// weight split buffer layout (elements per encoder)
#define W_QKV (DEPTH*3*DIMD*DIMD)
#define W_O   (DEPTH*DIMD*DIMD)
#define W_L1  (DEPTH*DFF*DIMD)
#define W_L2  (DEPTH*DIMD*DFF)
#define W_ENC (W_QKV+W_O+W_L1+W_L2)

// ---------------- static scratch ----------------
__device__ __align__(16) float g_x   [(size_t)NTOK_S * DIMD];
__device__ __align__(16) float g_qkv [(size_t)NTOK_S * 3 * DIMD];
__device__ __align__(16) float g_attn[(size_t)NTOK_S * DIMD];
__device__ __align__(16) float g_tmp [(size_t)NTOK_S * DIMD];
__device__ __align__(16) float g_h   [(size_t)NTOK_S * DFF];
__device__ __align__(16) __nv_bfloat16 g_whi[2 * W_ENC];
__device__ __align__(16) __nv_bfloat16 g_wlo[2 * W_ENC];

__device__ __forceinline__ uint32_t smem_u32(const void* p) {
    uint32_t a;
    asm("{ .reg .u64 t; cvta.to.shared.u64 t, %1; cvt.u32.u64 %0, t; }" : "=r"(a) : "l"(p));
    return a;
}
__device__ __forceinline__ uint32_t pack_bf2(float x, float y) {
    __nv_bfloat162 t = __floats2bfloat162_rn(x, y);
    return *reinterpret_cast<uint32_t*>(&t);
}

// ---------------- weight split: fp32 -> bf16 hi + lo ----------------
__global__ void split_kernel(const float* __restrict__ in, __nv_bfloat16* __restrict__ hi,
                             __nv_bfloat16* __restrict__ lo, int n)
{
    int i = blockIdx.x * 256 + threadIdx.x;
    if (i < n) {
        float v = in[i];
        __nv_bfloat16 h = __float2bfloat16(v);
        hi[i] = h;
        lo[i] = __float2bfloat16(v - __bfloat162float(h));
    }
}

// ---------------- HMMA GEMM: C[M,N] = act(A[M,K] @ W[N,K]^T + bias) ----------------
// CTA tile 128x128, BK=32. 8 warps as 2(M) x 4(N); warp tile 64x32.
// A fp32 -> bf16 hi/lo split in-kernel; W pre-split. acc += ah*bh + ah*bl + al*bh.
#define APITCH 80          // padded row stride (bytes) for 32 bf16 + 16B pad
#define PARTB  10240       // 128 rows * 80B, one hi or lo plane
#define BOFF   20480       // B region offset within a stage
#define STAGEB 40960       // A(hi+lo) + B(hi+lo)
#define GSMEM  (2*STAGEB)

#define LDSM4(R0,R1,R2,R3,ADDR) \
    asm volatile("ldmatrix.sync.aligned.m8n8.x4.shared.b16 {%0,%1,%2,%3}, [%4];" \
                 : "=r"(R0),"=r"(R1),"=r"(R2),"=r"(R3) : "r"(ADDR))

#define MMA16816(C, A0,A1,A2,A3, B0,B1) \
    asm volatile("mma.sync.aligned.m16n8k16.row.col.f32.bf16.bf16.f32 " \
                 "{%0,%1,%2,%3}, {%4,%5,%6,%7}, {%8,%9}, {%0,%1,%2,%3};" \
                 : "+f"((C)[0]),"+f"((C)[1]),"+f"((C)[2]),"+f"((C)[3]) \
                 : "r"(A0),"r"(A1),"r"(A2),"r"(A3), "r"(B0),"r"(B1))

__global__ void __launch_bounds__(256) gemm_mma(
    const float* __restrict__ A,
    const __nv_bfloat16* __restrict__ Bhi,
    const __nv_bfloat16* __restrict__ Blo,
    const float* __restrict__ bias,
    float* __restrict__ C,
    int M, int N, int K, int relu)
{
    extern __shared__ __align__(128) char smem[];
    const int tid  = threadIdx.x;
    const int lane = tid & 31;
    const int wid  = tid >> 5;
    const int warpM = wid >> 2;          // 0..1
    const int warpN = wid & 3;           // 0..3
    const int m0 = blockIdx.y * 128;
    const int n0 = blockIdx.x * 128;
    const uint32_t sb = smem_u32(smem);

    // loader mapping: thread -> (row 0..127, half 0..1); 16 elements per thread
    const int lrow = tid >> 1;
    const int lhalf = tid & 1;
    const float*         aptr = A   + (size_t)(m0 + lrow) * K + lhalf * 16;
    const __nv_bfloat16* bhp  = Bhi + (size_t)(n0 + lrow) * K + lhalf * 16;
    const __nv_bfloat16* blp  = Blo + (size_t)(n0 + lrow) * K + lhalf * 16;
    const uint32_t sts_off = (uint32_t)(lrow * APITCH + lhalf * 32);

    const int nch = K >> 5;

    float acc[4][4][4];
    #pragma unroll
    for (int i = 0; i < 4; i++)
        #pragma unroll
        for (int j = 0; j < 4; j++)
            #pragma unroll
            for (int q = 0; q < 4; q++) acc[i][j][q] = 0.f;

    float af[16];
    uint4 bhv[2], blv[2];

    // ---- prefetch chunk 0 ----
    {
        const float4* ap = (const float4*)aptr;
        float4 t0 = ap[0], t1 = ap[1], t2 = ap[2], t3 = ap[3];
        af[0]=t0.x; af[1]=t0.y; af[2]=t0.z; af[3]=t0.w;
        af[4]=t1.x; af[5]=t1.y; af[6]=t1.z; af[7]=t1.w;
        af[8]=t2.x; af[9]=t2.y; af[10]=t2.z; af[11]=t2.w;
        af[12]=t3.x; af[13]=t3.y; af[14]=t3.z; af[15]=t3.w;
        const uint4* bp = (const uint4*)bhp;
        bhv[0] = bp[0]; bhv[1] = bp[1];
        const uint4* lp = (const uint4*)blp;
        blv[0] = lp[0]; blv[1] = lp[1];
    }

    for (int c = 0; c < nch; c++) {
        // ---- STS chunk c from regs ----
        {
            const uint32_t stage = sb + (uint32_t)(c & 1) * STAGEB;
            uint32_t h[8], l[8];
            #pragma unroll
            for (int j = 0; j < 8; j++) {
                float v0 = af[2*j], v1 = af[2*j+1];
                __nv_bfloat16 h0 = __float2bfloat16(v0);
                __nv_bfloat16 h1 = __float2bfloat16(v1);
                h[j] = ((uint32_t)__bfloat16_as_ushort(h1) << 16) | __bfloat16_as_ushort(h0);
                l[j] = pack_bf2(v0 - __bfloat162float(h0), v1 - __bfloat162float(h1));
            }
            uint32_t a0 = stage + sts_off;
            asm volatile("st.shared.v4.b32 [%0], {%1,%2,%3,%4};" :: "r"(a0),      "r"(h[0]),"r"(h[1]),"r"(h[2]),"r"(h[3]) : "memory");
            asm volatile("st.shared.v4.b32 [%0], {%1,%2,%3,%4};" :: "r"(a0+16),   "r"(h[4]),"r"(h[5]),"r"(h[6]),"r"(h[7]) : "memory");
            asm volatile("st.shared.v4.b32 [%0], {%1,%2,%3,%4};" :: "r"(a0+PARTB),"r"(l[0]),"r"(l[1]),"r"(l[2]),"r"(l[3]) : "memory");
            asm volatile("st.shared.v4.b32 [%0], {%1,%2,%3,%4};" :: "r"(a0+PARTB+16),"r"(l[4]),"r"(l[5]),"r"(l[6]),"r"(l[7]) : "memory");
            uint32_t b0 = stage + BOFF + sts_off;
            asm volatile("st.shared.v4.b32 [%0], {%1,%2,%3,%4};" :: "r"(b0),      "r"(bhv[0].x),"r"(bhv[0].y),"r"(bhv[0].z),"r"(bhv[0].w) : "memory");
            asm volatile("st.shared.v4.b32 [%0], {%1,%2,%3,%4};" :: "r"(b0+16),   "r"(bhv[1].x),"r"(bhv[1].y),"r"(bhv[1].z),"r"(bhv[1].w) : "memory");
            asm volatile("st.shared.v4.b32 [%0], {%1,%2,%3,%4};" :: "r"(b0+PARTB),"r"(blv[0].x),"r"(blv[0].y),"r"(blv[0].z),"r"(blv[0].w) : "memory");
            asm volatile("st.shared.v4.b32 [%0], {%1,%2,%3,%4};" :: "r"(b0+PARTB+16),"r"(blv[1].x),"r"(blv[1].y),"r"(blv[1].z),"r"(blv[1].w) : "memory");
        }
        __syncthreads();

        // ---- LDG prefetch chunk c+1 ----
        if (c + 1 < nch) {
            const float4* ap = (const float4*)(aptr + (c + 1) * 32);
            float4 t0 = ap[0], t1 = ap[1], t2 = ap[2], t3 = ap[3];
            af[0]=t0.x; af[1]=t0.y; af[2]=t0.z; af[3]=t0.w;
            af[4]=t1.x; af[5]=t1.y; af[6]=t1.z; af[7]=t1.w;
            af[8]=t2.x; af[9]=t2.y; af[10]=t2.z; af[11]=t2.w;
            af[12]=t3.x; af[13]=t3.y; af[14]=t3.z; af[15]=t3.w;
            const uint4* bp = (const uint4*)(bhp + (c + 1) * 32);
            bhv[0] = bp[0]; bhv[1] = bp[1];
            const uint4* lp = (const uint4*)(blp + (c + 1) * 32);
            blv[0] = lp[0]; blv[1] = lp[1];
        }

        // ---- compute chunk c ----
        {
            const uint32_t stage = sb + (uint32_t)(c & 1) * STAGEB;
            #pragma unroll
            for (int ks = 0; ks < 2; ks++) {
                uint32_t ah[4][4], al[4][4];
                {
                    const int arow = warpM * 64 + (lane & 15);
                    const uint32_t abase = stage + (uint32_t)(ks * 32 + ((lane >> 4) & 1) * 16);
                    #pragma unroll
                    for (int mf = 0; mf < 4; mf++) {
                        uint32_t ad = abase + (uint32_t)((arow + mf * 16) * APITCH);
                        LDSM4(ah[mf][0], ah[mf][1], ah[mf][2], ah[mf][3], ad);
                        LDSM4(al[mf][0], al[mf][1], al[mf][2], al[mf][3], ad + PARTB);
                    }
                }
                uint32_t bh[4][2], bl[4][2];
                {
                    const int nrow = warpN * 32 + ((lane >> 4) & 1) * 8 + (lane & 7);
                    const uint32_t bbase = stage + BOFF + (uint32_t)(ks * 32 + ((lane >> 3) & 1) * 16);
                    #pragma unroll
                    for (int np = 0; np < 2; np++) {
                        uint32_t bd = bbase + (uint32_t)((nrow + np * 16) * APITCH);
                        LDSM4(bh[2*np][0], bh[2*np][1], bh[2*np+1][0], bh[2*np+1][1], bd);
                        LDSM4(bl[2*np][0], bl[2*np][1], bl[2*np+1][0], bl[2*np+1][1], bd + PARTB);
                    }
                }
                #pragma unroll
                for (int mf = 0; mf < 4; mf++)
                    #pragma unroll
                    for (int nf = 0; nf < 4; nf++) {
                        MMA16816(acc[mf][nf], ah[mf][0],ah[mf][1],ah[mf][2],ah[mf][3], bh[nf][0],bh[nf][1]);
                        MMA16816(acc[mf][nf], ah[mf][0],ah[mf][1],ah[mf][2],ah[mf][3], bl[nf][0],bl[nf][1]);
                        MMA16816(acc[mf][nf], al[mf][0],al[mf][1],al[mf][2],al[mf][3], bh[nf][0],bh[nf][1]);
                    }
            }
        }
        __syncthreads();
    }

    // ---- epilogue: bias (+relu), direct coalesced float2 stores ----
    #pragma unroll
    for (int nf = 0; nf < 4; nf++) {
        const int col = n0 + warpN * 32 + nf * 8 + (lane & 3) * 2;
        const float b0 = bias[col], b1 = bias[col + 1];
        #pragma unroll
        for (int mf = 0; mf < 4; mf++) {
            const int r0 = m0 + warpM * 64 + mf * 16 + (lane >> 2);
            float v0 = acc[mf][nf][0] + b0;
            float v1 = acc[mf][nf][1] + b1;
            float v2 = acc[mf][nf][2] + b0;
            float v3 = acc[mf][nf][3] + b1;
            if (relu) {
                v0 = fmaxf(v0, 0.f); v1 = fmaxf(v1, 0.f);
                v2 = fmaxf(v2, 0.f); v3 = fmaxf(v3, 0.f);
            }
            float2 p0 = make_float2(v0, v1);
            float2 p1 = make_float2(v2, v3);
            *(float2*)(C + (size_t)r0 * N + col) = p0;
            *(float2*)(C + (size_t)(r0 + 8) * N + col) = p1;
        }
    }
}

// ---------------- embed: gelu(moveinfo @ w_in^T + b_in) + cls assembly ----------------
__global__ void embed_kernel(const float* __restrict__ mi, const int* __restrict__ sse,
                             const float* __restrict__ w_in, const float* __restrict__ b_in,
                             float* __restrict__ x)
{
    size_t gid = (size_t)blockIdx.x * 256 + threadIdx.x;
    int d   = (int)(gid & 255);
    int tok = (int)(gid >> 8);
    int r   = tok % SQ_S;
    int seq = tok / SQ_S;
    int s   = seq & (SS - 1);
    int t   = seq >> 8;
    float val;
    if (r == 0) {
        val = 1e-5f;
    } else {
        int n = sse[2 * s] + (r - 1);
        const float* mp = mi + ((size_t)n * TT + t) * 2;
        float z = mp[0] * w_in[d * 2 + 0] + mp[1] * w_in[d * 2 + 1] + b_in[d];
        val = 0.5f * z * (1.0f + erff(z * 0.70710678118654752f));
    }
    x[gid] = val;
}

// ---------------- attention: per (sequence, head), Sq <= 64, HD = 32 ----------------
__global__ void attn_kernel(const float* __restrict__ qkv, float* __restrict__ out, int Sq)
{
    const int seq  = blockIdx.x;
    const int head = blockIdx.y;
    const int tid  = threadIdx.x;
    const int lane = tid & 31;
    const int w    = tid >> 5;

    __shared__ float Ks[64][33];
    __shared__ float Vs[64][33];
    __shared__ float qs[4][33];
    __shared__ float ps[4][64];

    const float* base = qkv + (size_t)seq * Sq * (3 * DIMD) + head * HD;

    for (int idx = tid; idx < Sq * HD; idx += 128) {
        int rr = idx >> 5, dd = idx & 31;
        Ks[rr][dd] = base[(size_t)rr * (3 * DIMD) + DIMD + dd];
        Vs[rr][dd] = base[(size_t)rr * (3 * DIMD) + 2 * DIMD + dd];
    }
    __syncthreads();

    const float scale = 0.17677669529663689f;

    for (int i = w; i < Sq; i += 4) {
        qs[w][lane] = base[(size_t)i * (3 * DIMD) + lane];
        __syncwarp();
        float sc0 = -1e30f, sc1 = -1e30f;
        if (lane < Sq) {
            float sacc = 0.f;
            #pragma unroll
            for (int dd = 0; dd < HD; dd++) sacc += qs[w][dd] * Ks[lane][dd];
            sc0 = sacc * scale;
        }
        int j1 = lane + 32;
        if (j1 < Sq) {
            float sacc = 0.f;
            #pragma unroll
            for (int dd = 0; dd < HD; dd++) sacc += qs[w][dd] * Ks[j1][dd];
            sc1 = sacc * scale;
        }
        float mx = fmaxf(sc0, sc1);
        #pragma unroll
        for (int o = 16; o; o >>= 1) mx = fmaxf(mx, __shfl_xor_sync(0xffffffffu, mx, o));
        float e0 = (lane < Sq) ? expf(sc0 - mx) : 0.f;
        float e1 = (j1 < Sq) ? expf(sc1 - mx) : 0.f;
        float se = e0 + e1;
        #pragma unroll
        for (int o = 16; o; o >>= 1) se += __shfl_xor_sync(0xffffffffu, se, o);
        float inv = 1.f / se;
        if (lane < Sq) ps[w][lane] = e0 * inv;
        if (j1 < Sq)   ps[w][j1]   = e1 * inv;
        __syncwarp();
        float acc = 0.f;
        for (int j = 0; j < Sq; j++) acc += ps[w][j] * Vs[j][lane];
        out[((size_t)seq * Sq + i) * DIMD + head * HD + lane] = acc;
        __syncwarp();
    }
}

// ---------------- fused residual + LayerNorm ----------------
__global__ void add_ln_kernel(const float* __restrict__ X, const float* __restrict__ H,
                              const float* __restrict__ w, const float* __restrict__ b,
                              float* __restrict__ out)
{
    const int row = blockIdx.x;
    const int tid = threadIdx.x;
    float v = X[(size_t)row * DIMD + tid] + H[(size_t)row * DIMD + tid];
    float s = v, s2 = v * v;
    #pragma unroll
    for (int o = 16; o; o >>= 1) {
        s  += __shfl_xor_sync(0xffffffffu, s,  o);
        s2 += __shfl_xor_sync(0xffffffffu, s2, o);
    }
    __shared__ float ws[8], ws2[8];
    if ((tid & 31) == 0) { ws[tid >> 5] = s; ws2[tid >> 5] = s2; }
    __syncthreads();
    float ts = 0.f, ts2 = 0.f;
    #pragma unroll
    for (int i = 0; i < 8; i++) { ts += ws[i]; ts2 += ws2[i]; }
    float mean = ts * (1.0f / DIMD);
    float var  = ts2 * (1.0f / DIMD) - mean * mean;
    out[(size_t)row * DIMD + tid] = (v - mean) * rsqrtf(var + 1e-5f) * w[tid] + b[tid];
}

// ---------------- cls extraction ----------------
__global__ void extract_cls_kernel(const float* __restrict__ x, float* __restrict__ tx)
{
    size_t gid = (size_t)blockIdx.x * 256 + threadIdx.x;
    int d   = (int)(gid & 255);
    int tok = (int)(gid >> 8);
    int t = tok & (TT - 1);
    int s = tok >> 6;
    tx[gid] = x[(((size_t)t * SS + s) * SQ_S) * DIMD + d];
}

// ---------------- host orchestration ----------------
struct LayerW {
    const float *qkvb, *ob, *l1b, *l2b, *ln1w, *ln1b, *ln2w, *ln2b;
    const __nv_bfloat16 *qkvw_hi, *qkvw_lo, *ow_hi, *ow_lo, *l1w_hi, *l1w_lo, *l2w_hi, *l2w_lo;
};

static inline void launch_gemm(const float* A, const __nv_bfloat16* bh, const __nv_bfloat16* bl,
                               const float* bias, float* C, int M, int N, int K, int relu)
{
    dim3 grid(N / 128, M / 128);
    gemm_mma<<<grid, 256, GSMEM>>>(A, bh, bl, bias, C, M, N, K, relu);
}

static void run_layer(float* x, float* qkv, float* attnb, float* tmp, float* h,
                      const LayerW& L, int nseq, int Sq, float* final_out)
{
    const int ntok = nseq * Sq;
    launch_gemm(x, L.qkvw_hi, L.qkvw_lo, L.qkvb, qkv, ntok, 3 * DIMD, DIMD, 0);
    attn_kernel<<<dim3(nseq, HEADS), 128>>>(qkv, attnb, Sq);
    launch_gemm(attnb, L.ow_hi, L.ow_lo, L.ob, tmp, ntok, DIMD, DIMD, 0);
    add_ln_kernel<<<ntok, DIMD>>>(x, tmp, L.ln1w, L.ln1b, x);
    launch_gemm(x, L.l1w_hi, L.l1w_lo, L.l1b, h, ntok, DFF, DIMD, 1);
    launch_gemm(h, L.l2w_hi, L.l2w_lo, L.l2b, tmp, ntok, DIMD, DFF, 0);
    add_ln_kernel<<<ntok, DIMD>>>(x, tmp, L.ln2w, L.ln2b, final_out ? final_out : x);
}

static LayerW make_layer(const float* const* p, int l, const __nv_bfloat16* whi,
                         const __nv_bfloat16* wlo, int enc)
{
    LayerW L;
    L.qkvb = p[1]  + (size_t)l * 3 * DIMD;
    L.ob   = p[3]  + (size_t)l * DIMD;
    L.l1b  = p[5]  + (size_t)l * DFF;
    L.l2b  = p[7]  + (size_t)l * DIMD;
    L.ln1w = p[8]  + (size_t)l * DIMD;
    L.ln1b = p[9]  + (size_t)l * DIMD;
    L.ln2w = p[10] + (size_t)l * DIMD;
    L.ln2b = p[11] + (size_t)l * DIMD;
    size_t eb = (size_t)enc * W_ENC;
    L.qkvw_hi = whi + eb + (size_t)l * 3 * DIMD * DIMD;
    L.qkvw_lo = wlo + eb + (size_t)l * 3 * DIMD * DIMD;
    L.ow_hi   = whi + eb + W_QKV + (size_t)l * DIMD * DIMD;
    L.ow_lo   = wlo + eb + W_QKV + (size_t)l * DIMD * DIMD;
    L.l1w_hi  = whi + eb + W_QKV + W_O + (size_t)l * DFF * DIMD;
    L.l1w_lo  = wlo + eb + W_QKV + W_O + (size_t)l * DFF * DIMD;
    L.l2w_hi  = whi + eb + W_QKV + W_O + W_L1 + (size_t)l * DIMD * DFF;
    L.l2w_lo  = wlo + eb + W_QKV + W_O + W_L1 + (size_t)l * DIMD * DFF;
    return L;
}

extern "C" void kernel_launch(void* const* d_in, const int* in_sizes, int n_in,
                              void* d_out, int out_size)
{
    const float* moveinfo = (const float*)d_in[0];
    const int*   sse      = (const int*)  d_in[1];
    const float* w_in     = (const float*)d_in[2];
    const float* b_in     = (const float*)d_in[3];
    const float* sp[12];
    const float* tp[12];
    for (int i = 0; i < 12; i++) sp[i] = (const float*)d_in[4 + i];
    for (int i = 0; i < 12; i++) tp[i] = (const float*)d_in[16 + i];

    float *x, *qkv, *attnb, *tmp, *h;
    __nv_bfloat16 *whi, *wlo;
    cudaGetSymbolAddress((void**)&x,     g_x);
    cudaGetSymbolAddress((void**)&qkv,   g_qkv);
    cudaGetSymbolAddress((void**)&attnb, g_attn);
    cudaGetSymbolAddress((void**)&tmp,   g_tmp);
    cudaGetSymbolAddress((void**)&h,     g_h);
    cudaGetSymbolAddress((void**)&whi,   g_whi);
    cudaGetSymbolAddress((void**)&wlo,   g_wlo);

    cudaFuncSetAttribute(gemm_mma, cudaFuncAttributeMaxDynamicSharedMemorySize, GSMEM);

    // 0) pre-split all GEMM weights to bf16 hi/lo
    struct { const float* src; size_t off; int n; } splits[8] = {
        { sp[0], 0,                          W_QKV },
        { sp[2], W_QKV,                      W_O   },
        { sp[4], W_QKV + W_O,                W_L1  },
        { sp[6], W_QKV + W_O + W_L1,         W_L2  },
        { tp[0], W_ENC,                      W_QKV },
        { tp[2], W_ENC + W_QKV,              W_O   },
        { tp[4], W_ENC + W_QKV + W_O,        W_L1  },
        { tp[6], W_ENC + W_QKV + W_O + W_L1, W_L2  },
    };
    for (int i = 0; i < 8; i++)
        split_kernel<<<(splits[i].n + 255) / 256, 256>>>(splits[i].src,
            whi + splits[i].off, wlo + splits[i].off, splits[i].n);

    // 1) embed
    embed_kernel<<<NTOK_S, 256>>>(moveinfo, sse, w_in, b_in, x);

    // 2) spatial encoder
    for (int l = 0; l < DEPTH; l++) {
        LayerW L = make_layer(sp, l, whi, wlo, 0);
        run_layer(x, qkv, attnb, tmp, h, L, NSEQ_S, SQ_S, nullptr);
    }

    // 3) cls extraction
    extract_cls_kernel<<<NTOK_T, 256>>>(x, tmp);

    // 4) temporal encoder
    for (int l = 0; l < DEPTH; l++) {
        LayerW L = make_layer(tp, l, whi, wlo, 1);
        const int ntok = NTOK_T;
        launch_gemm(tmp, L.qkvw_hi, L.qkvw_lo, L.qkvb, qkv, ntok, 3 * DIMD, DIMD, 0);
        attn_kernel<<<dim3(NSEQ_T, HEADS), 128>>>(qkv, x, SQ_T);
        launch_gemm(x, L.ow_hi, L.ow_lo, L.ob, attnb, ntok, DIMD, DIMD, 0);
        add_ln_kernel<<<ntok, DIMD>>>(tmp, attnb, L.ln1w, L.ln1b, tmp);
        launch_gemm(tmp, L.l1w_hi, L.l1w_lo, L.l1b, h, ntok, DFF, DIMD, 1);
        launch_gemm(h, L.l2w_hi, L.l2w_lo, L.l2b, attnb, ntok, DIMD, DFF, 0);
        float* outp = (l == DEPTH - 1) ? (float*)d_out : tmp;
        add_ln_kernel<<<ntok, DIMD>>>(tmp, attnb, L.ln2w, L.ln2b, outp);
    }
}

// round 4
// speedup vs baseline: 2.0033x; 1.1420x over previous
#include <cuda_runtime.h>
#include <cuda_bf16.h>
#include <cstdint>

// ---------------- problem constants ----------------
#define DIMD   256
#define HEADS  8
#define HD     32
#define DEPTH  2
#define DFF    128
#define TT     64
#define SS     256
#define LL     8
#define NSEQ_S (TT*SS)
#define SQ_S   (1+LL)
#define NTOK_S (NSEQ_S*SQ_S)    // 147456
#define NSEQ_T SS
#define SQ_T   TT
#define NTOK_T (NSEQ_T*SQ_T)    // 16384

#define W_QKV (DEPTH*3*DIMD*DIMD)
#define W_O   (DEPTH*DIMD*DIMD)
#define W_L1  (DEPTH*DFF*DIMD)
#define W_L2  (DEPTH*DIMD*DFF)
#define W_ENC (W_QKV+W_O+W_L1+W_L2)

// ---------------- static scratch ----------------
__device__ __align__(16) float g_x   [(size_t)NTOK_S * DIMD];
__device__ __align__(16) float g_qkv [(size_t)NTOK_S * 3 * DIMD];
__device__ __align__(16) float g_attn[(size_t)NTOK_S * DIMD];
__device__ __align__(16) float g_tmp [(size_t)NTOK_S * DIMD];
__device__ __align__(16) float g_h   [(size_t)NTOK_S * DFF];
__device__ __align__(16) __nv_bfloat16 g_whi[2 * W_ENC];
__device__ __align__(16) __nv_bfloat16 g_wlo[2 * W_ENC];

__device__ __forceinline__ uint32_t smem_u32(const void* p) {
    uint32_t a;
    asm("{ .reg .u64 t; cvta.to.shared.u64 t, %1; cvt.u32.u64 %0, t; }" : "=r"(a) : "l"(p));
    return a;
}
__device__ __forceinline__ uint32_t pack_bf2(float x, float y) {
    __nv_bfloat162 t = __floats2bfloat162_rn(x, y);
    return *reinterpret_cast<uint32_t*>(&t);
}

#define LDSM4(R0,R1,R2,R3,ADDR) \
    asm volatile("ldmatrix.sync.aligned.m8n8.x4.shared.b16 {%0,%1,%2,%3}, [%4];" \
                 : "=r"(R0),"=r"(R1),"=r"(R2),"=r"(R3) : "r"(ADDR))

#define MMA16816(C, A0,A1,A2,A3, B0,B1) \
    asm volatile("mma.sync.aligned.m16n8k16.row.col.f32.bf16.bf16.f32 " \
                 "{%0,%1,%2,%3}, {%4,%5,%6,%7}, {%8,%9}, {%0,%1,%2,%3};" \
                 : "+f"((C)[0]),"+f"((C)[1]),"+f"((C)[2]),"+f"((C)[3]) \
                 : "r"(A0),"r"(A1),"r"(A2),"r"(A3), "r"(B0),"r"(B1))

#define CP_ASYNC16(DST, SRC) \
    asm volatile("cp.async.ca.shared.global [%0], [%1], 16;" :: "r"(DST), "l"(SRC))
#define CP_COMMIT()  asm volatile("cp.async.commit_group;" ::: "memory")
#define CP_WAIT1()   asm volatile("cp.async.wait_group 1;" ::: "memory")

// ---------------- weight split (two tensors per launch) ----------------
__global__ void split2_kernel(const float* __restrict__ s0, __nv_bfloat16* __restrict__ h0,
                              __nv_bfloat16* __restrict__ l0, int n0,
                              const float* __restrict__ s1, __nv_bfloat16* __restrict__ h1,
                              __nv_bfloat16* __restrict__ l1, int n1)
{
    const float* s = blockIdx.y ? s1 : s0;
    __nv_bfloat16* hh = blockIdx.y ? h1 : h0;
    __nv_bfloat16* ll = blockIdx.y ? l1 : l0;
    int n = blockIdx.y ? n1 : n0;
    int i = blockIdx.x * 256 + threadIdx.x;
    if (i < n) {
        float v = s[i];
        __nv_bfloat16 h = __float2bfloat16(v);
        hh[i] = h;
        ll[i] = __float2bfloat16(v - __bfloat162float(h));
    }
}

// ========================================================================
// gemm_mma: C[M,N] = act(A @ W^T + bias).  CTA 128x128, BK=32, 8 warps 2x4.
// ========================================================================
#define APITCH 80
#define PARTB  10240
#define BOFF   20480
#define STAGEB 40960
#define GSMEM  (2*STAGEB)

__global__ void __launch_bounds__(256) gemm_mma(
    const float* __restrict__ A,
    const __nv_bfloat16* __restrict__ Bhi,
    const __nv_bfloat16* __restrict__ Blo,
    const float* __restrict__ bias,
    float* __restrict__ C,
    int M, int N, int K, int relu)
{
    extern __shared__ __align__(128) char smem[];
    const int tid  = threadIdx.x;
    const int lane = tid & 31;
    const int wid  = tid >> 5;
    const int warpM = wid >> 2;
    const int warpN = wid & 3;
    const int m0 = blockIdx.y * 128;
    const int n0 = blockIdx.x * 128;
    const uint32_t sb = smem_u32(smem);

    const int lrow = tid >> 1;
    const int lhalf = tid & 1;
    const float*         aptr = A   + (size_t)(m0 + lrow) * K + lhalf * 16;
    const __nv_bfloat16* bhp  = Bhi + (size_t)(n0 + lrow) * K + lhalf * 16;
    const __nv_bfloat16* blp  = Blo + (size_t)(n0 + lrow) * K + lhalf * 16;
    const uint32_t sts_off = (uint32_t)(lrow * APITCH + lhalf * 32);

    const int nch = K >> 5;

    float acc[4][4][4];
    #pragma unroll
    for (int i = 0; i < 4; i++)
        #pragma unroll
        for (int j = 0; j < 4; j++)
            #pragma unroll
            for (int q = 0; q < 4; q++) acc[i][j][q] = 0.f;

    float af[16];
    uint4 bhv[2], blv[2];
    {
        const float4* ap = (const float4*)aptr;
        float4 t0 = ap[0], t1 = ap[1], t2 = ap[2], t3 = ap[3];
        af[0]=t0.x; af[1]=t0.y; af[2]=t0.z; af[3]=t0.w;
        af[4]=t1.x; af[5]=t1.y; af[6]=t1.z; af[7]=t1.w;
        af[8]=t2.x; af[9]=t2.y; af[10]=t2.z; af[11]=t2.w;
        af[12]=t3.x; af[13]=t3.y; af[14]=t3.z; af[15]=t3.w;
        const uint4* bp = (const uint4*)bhp;
        bhv[0] = bp[0]; bhv[1] = bp[1];
        const uint4* lp = (const uint4*)blp;
        blv[0] = lp[0]; blv[1] = lp[1];
    }

    for (int c = 0; c < nch; c++) {
        {
            const uint32_t stage = sb + (uint32_t)(c & 1) * STAGEB;
            uint32_t h[8], l[8];
            #pragma unroll
            for (int j = 0; j < 8; j++) {
                float v0 = af[2*j], v1 = af[2*j+1];
                __nv_bfloat16 h0 = __float2bfloat16(v0);
                __nv_bfloat16 h1 = __float2bfloat16(v1);
                h[j] = ((uint32_t)__bfloat16_as_ushort(h1) << 16) | __bfloat16_as_ushort(h0);
                l[j] = pack_bf2(v0 - __bfloat162float(h0), v1 - __bfloat162float(h1));
            }
            uint32_t a0 = stage + sts_off;
            asm volatile("st.shared.v4.b32 [%0], {%1,%2,%3,%4};" :: "r"(a0),      "r"(h[0]),"r"(h[1]),"r"(h[2]),"r"(h[3]) : "memory");
            asm volatile("st.shared.v4.b32 [%0], {%1,%2,%3,%4};" :: "r"(a0+16),   "r"(h[4]),"r"(h[5]),"r"(h[6]),"r"(h[7]) : "memory");
            asm volatile("st.shared.v4.b32 [%0], {%1,%2,%3,%4};" :: "r"(a0+PARTB),"r"(l[0]),"r"(l[1]),"r"(l[2]),"r"(l[3]) : "memory");
            asm volatile("st.shared.v4.b32 [%0], {%1,%2,%3,%4};" :: "r"(a0+PARTB+16),"r"(l[4]),"r"(l[5]),"r"(l[6]),"r"(l[7]) : "memory");
            uint32_t b0 = stage + BOFF + sts_off;
            asm volatile("st.shared.v4.b32 [%0], {%1,%2,%3,%4};" :: "r"(b0),      "r"(bhv[0].x),"r"(bhv[0].y),"r"(bhv[0].z),"r"(bhv[0].w) : "memory");
            asm volatile("st.shared.v4.b32 [%0], {%1,%2,%3,%4};" :: "r"(b0+16),   "r"(bhv[1].x),"r"(bhv[1].y),"r"(bhv[1].z),"r"(bhv[1].w) : "memory");
            asm volatile("st.shared.v4.b32 [%0], {%1,%2,%3,%4};" :: "r"(b0+PARTB),"r"(blv[0].x),"r"(blv[0].y),"r"(blv[0].z),"r"(blv[0].w) : "memory");
            asm volatile("st.shared.v4.b32 [%0], {%1,%2,%3,%4};" :: "r"(b0+PARTB+16),"r"(blv[1].x),"r"(blv[1].y),"r"(blv[1].z),"r"(blv[1].w) : "memory");
        }
        __syncthreads();

        if (c + 1 < nch) {
            const float4* ap = (const float4*)(aptr + (c + 1) * 32);
            float4 t0 = ap[0], t1 = ap[1], t2 = ap[2], t3 = ap[3];
            af[0]=t0.x; af[1]=t0.y; af[2]=t0.z; af[3]=t0.w;
            af[4]=t1.x; af[5]=t1.y; af[6]=t1.z; af[7]=t1.w;
            af[8]=t2.x; af[9]=t2.y; af[10]=t2.z; af[11]=t2.w;
            af[12]=t3.x; af[13]=t3.y; af[14]=t3.z; af[15]=t3.w;
            const uint4* bp = (const uint4*)(bhp + (c + 1) * 32);
            bhv[0] = bp[0]; bhv[1] = bp[1];
            const uint4* lp = (const uint4*)(blp + (c + 1) * 32);
            blv[0] = lp[0]; blv[1] = lp[1];
        }

        {
            const uint32_t stage = sb + (uint32_t)(c & 1) * STAGEB;
            #pragma unroll
            for (int ks = 0; ks < 2; ks++) {
                uint32_t ah[4][4], al[4][4];
                {
                    const int arow = warpM * 64 + (lane & 15);
                    const uint32_t abase = stage + (uint32_t)(ks * 32 + ((lane >> 4) & 1) * 16);
                    #pragma unroll
                    for (int mf = 0; mf < 4; mf++) {
                        uint32_t ad = abase + (uint32_t)((arow + mf * 16) * APITCH);
                        LDSM4(ah[mf][0], ah[mf][1], ah[mf][2], ah[mf][3], ad);
                        LDSM4(al[mf][0], al[mf][1], al[mf][2], al[mf][3], ad + PARTB);
                    }
                }
                uint32_t bh[4][2], bl[4][2];
                {
                    const int nrow = warpN * 32 + ((lane >> 4) & 1) * 8 + (lane & 7);
                    const uint32_t bbase = stage + BOFF + (uint32_t)(ks * 32 + ((lane >> 3) & 1) * 16);
                    #pragma unroll
                    for (int np = 0; np < 2; np++) {
                        uint32_t bd = bbase + (uint32_t)((nrow + np * 16) * APITCH);
                        LDSM4(bh[2*np][0], bh[2*np][1], bh[2*np+1][0], bh[2*np+1][1], bd);
                        LDSM4(bl[2*np][0], bl[2*np][1], bl[2*np+1][0], bl[2*np+1][1], bd + PARTB);
                    }
                }
                #pragma unroll
                for (int mf = 0; mf < 4; mf++)
                    #pragma unroll
                    for (int nf = 0; nf < 4; nf++) {
                        MMA16816(acc[mf][nf], ah[mf][0],ah[mf][1],ah[mf][2],ah[mf][3], bh[nf][0],bh[nf][1]);
                        MMA16816(acc[mf][nf], ah[mf][0],ah[mf][1],ah[mf][2],ah[mf][3], bl[nf][0],bl[nf][1]);
                        MMA16816(acc[mf][nf], al[mf][0],al[mf][1],al[mf][2],al[mf][3], bh[nf][0],bh[nf][1]);
                    }
            }
        }
        __syncthreads();
    }

    #pragma unroll
    for (int nf = 0; nf < 4; nf++) {
        const int col = n0 + warpN * 32 + nf * 8 + (lane & 3) * 2;
        const float b0 = bias[col], b1 = bias[col + 1];
        #pragma unroll
        for (int mf = 0; mf < 4; mf++) {
            const int r0 = m0 + warpM * 64 + mf * 16 + (lane >> 2);
            float v0 = acc[mf][nf][0] + b0;
            float v1 = acc[mf][nf][1] + b1;
            float v2 = acc[mf][nf][2] + b0;
            float v3 = acc[mf][nf][3] + b1;
            if (relu) {
                v0 = fmaxf(v0, 0.f); v1 = fmaxf(v1, 0.f);
                v2 = fmaxf(v2, 0.f); v3 = fmaxf(v3, 0.f);
            }
            *(float2*)(C + (size_t)r0 * N + col) = make_float2(v0, v1);
            *(float2*)(C + (size_t)(r0 + 8) * N + col) = make_float2(v2, v3);
        }
    }
}

// ========================================================================
// gemm_mma_ln: Out[M,256] = LN(Xres + (A @ W^T + bias)) * lnw + lnb
// CTA 128x256 (full row), BK=32, 8 warps 2x4 (warp tile 64x64).
// B loads via cp.async. In-place Out==Xres safe (CTA covers full rows).
// ========================================================================
#define L_PA   10240            // A lo-plane offset
#define L_BO   20480            // B region offset
#define L_PB   20480            // B lo-plane offset within B region
#define L_STG  61440            // stage bytes
#define L_SMEM (2*L_STG)

__global__ void __launch_bounds__(256) gemm_mma_ln(
    const float* __restrict__ A,
    const __nv_bfloat16* __restrict__ Bhi,
    const __nv_bfloat16* __restrict__ Blo,
    const float* __restrict__ bias,
    const float* __restrict__ Xres,
    const float* __restrict__ lnw,
    const float* __restrict__ lnb,
    float* __restrict__ Out,
    int M, int K)
{
    extern __shared__ __align__(128) char smem[];
    const int tid  = threadIdx.x;
    const int lane = tid & 31;
    const int wid  = tid >> 5;
    const int warpM = wid >> 2;
    const int warpN = wid & 3;
    const int m0 = blockIdx.x * 128;
    const uint32_t sb = smem_u32(smem);

    // A loader: 128 rows, 2 threads/row
    const int lrow = tid >> 1;
    const int lhalf = tid & 1;
    const float* aptr = A + (size_t)(m0 + lrow) * K + lhalf * 16;
    const uint32_t a_sts = (uint32_t)(lrow * APITCH + lhalf * 32);
    // B loader: 256 rows, 1 thread/row, 64B per plane per chunk via cp.async
    const char* bh_row = (const char*)(Bhi + (size_t)tid * K);
    const char* bl_row = (const char*)(Blo + (size_t)tid * K);
    const uint32_t b_sts = (uint32_t)(tid * APITCH);

    const int nch = K >> 5;

    float acc[4][8][4];
    #pragma unroll
    for (int i = 0; i < 4; i++)
        #pragma unroll
        for (int j = 0; j < 8; j++)
            #pragma unroll
            for (int q = 0; q < 4; q++) acc[i][j][q] = 0.f;

    float af[16];
    // prefetch A(0); cp.async B(0)
    {
        const float4* ap = (const float4*)aptr;
        float4 t0 = ap[0], t1 = ap[1], t2 = ap[2], t3 = ap[3];
        af[0]=t0.x; af[1]=t0.y; af[2]=t0.z; af[3]=t0.w;
        af[4]=t1.x; af[5]=t1.y; af[6]=t1.z; af[7]=t1.w;
        af[8]=t2.x; af[9]=t2.y; af[10]=t2.z; af[11]=t2.w;
        af[12]=t3.x; af[13]=t3.y; af[14]=t3.z; af[15]=t3.w;
        uint32_t bd = sb + L_BO + b_sts;
        #pragma unroll
        for (int j = 0; j < 4; j++) {
            CP_ASYNC16(bd + j*16,        bh_row + j*16);
            CP_ASYNC16(bd + L_PB + j*16, bl_row + j*16);
        }
        CP_COMMIT();
    }

    for (int c = 0; c < nch; c++) {
        const uint32_t stage = sb + (uint32_t)(c & 1) * L_STG;
        // STS A(c) split from regs
        {
            uint32_t h[8], l[8];
            #pragma unroll
            for (int j = 0; j < 8; j++) {
                float v0 = af[2*j], v1 = af[2*j+1];
                __nv_bfloat16 h0 = __float2bfloat16(v0);
                __nv_bfloat16 h1 = __float2bfloat16(v1);
                h[j] = ((uint32_t)__bfloat16_as_ushort(h1) << 16) | __bfloat16_as_ushort(h0);
                l[j] = pack_bf2(v0 - __bfloat162float(h0), v1 - __bfloat162float(h1));
            }
            uint32_t a0 = stage + a_sts;
            asm volatile("st.shared.v4.b32 [%0], {%1,%2,%3,%4};" :: "r"(a0),       "r"(h[0]),"r"(h[1]),"r"(h[2]),"r"(h[3]) : "memory");
            asm volatile("st.shared.v4.b32 [%0], {%1,%2,%3,%4};" :: "r"(a0+16),    "r"(h[4]),"r"(h[5]),"r"(h[6]),"r"(h[7]) : "memory");
            asm volatile("st.shared.v4.b32 [%0], {%1,%2,%3,%4};" :: "r"(a0+L_PA),  "r"(l[0]),"r"(l[1]),"r"(l[2]),"r"(l[3]) : "memory");
            asm volatile("st.shared.v4.b32 [%0], {%1,%2,%3,%4};" :: "r"(a0+L_PA+16),"r"(l[4]),"r"(l[5]),"r"(l[6]),"r"(l[7]) : "memory");
        }
        // cp.async B(c+1) into other stage
        if (c + 1 < nch) {
            uint32_t bd = sb + (uint32_t)((c + 1) & 1) * L_STG + L_BO + b_sts;
            const char* sh = bh_row + (size_t)(c + 1) * 64;
            const char* sl = bl_row + (size_t)(c + 1) * 64;
            #pragma unroll
            for (int j = 0; j < 4; j++) {
                CP_ASYNC16(bd + j*16,        sh + j*16);
                CP_ASYNC16(bd + L_PB + j*16, sl + j*16);
            }
        }
        CP_COMMIT();
        CP_WAIT1();             // B(c) resident
        __syncthreads();

        // LDG A(c+1)
        if (c + 1 < nch) {
            const float4* ap = (const float4*)(aptr + (c + 1) * 32);
            float4 t0 = ap[0], t1 = ap[1], t2 = ap[2], t3 = ap[3];
            af[0]=t0.x; af[1]=t0.y; af[2]=t0.z; af[3]=t0.w;
            af[4]=t1.x; af[5]=t1.y; af[6]=t1.z; af[7]=t1.w;
            af[8]=t2.x; af[9]=t2.y; af[10]=t2.z; af[11]=t2.w;
            af[12]=t3.x; af[13]=t3.y; af[14]=t3.z; af[15]=t3.w;
        }

        // compute chunk c
        #pragma unroll
        for (int ks = 0; ks < 2; ks++) {
            uint32_t ah[4][4], al[4][4];
            {
                const int arow = warpM * 64 + (lane & 15);
                const uint32_t abase = stage + (uint32_t)(ks * 32 + ((lane >> 4) & 1) * 16);
                #pragma unroll
                for (int mf = 0; mf < 4; mf++) {
                    uint32_t ad = abase + (uint32_t)((arow + mf * 16) * APITCH);
                    LDSM4(ah[mf][0], ah[mf][1], ah[mf][2], ah[mf][3], ad);
                    LDSM4(al[mf][0], al[mf][1], al[mf][2], al[mf][3], ad + L_PA);
                }
            }
            #pragma unroll
            for (int np = 0; np < 4; np++) {
                const int nrow = warpN * 64 + np * 16 + ((lane >> 4) & 1) * 8 + (lane & 7);
                const uint32_t bd = stage + L_BO + (uint32_t)(ks * 32 + ((lane >> 3) & 1) * 16)
                                  + (uint32_t)(nrow * APITCH);
                uint32_t p0, p1, p2, p3, q0, q1, q2, q3;
                LDSM4(p0, p1, p2, p3, bd);
                LDSM4(q0, q1, q2, q3, bd + L_PB);
                #pragma unroll
                for (int mf = 0; mf < 4; mf++) {
                    MMA16816(acc[mf][2*np],   ah[mf][0],ah[mf][1],ah[mf][2],ah[mf][3], p0,p1);
                    MMA16816(acc[mf][2*np],   ah[mf][0],ah[mf][1],ah[mf][2],ah[mf][3], q0,q1);
                    MMA16816(acc[mf][2*np],   al[mf][0],al[mf][1],al[mf][2],al[mf][3], p0,p1);
                    MMA16816(acc[mf][2*np+1], ah[mf][0],ah[mf][1],ah[mf][2],ah[mf][3], p2,p3);
                    MMA16816(acc[mf][2*np+1], ah[mf][0],ah[mf][1],ah[mf][2],ah[mf][3], q2,q3);
                    MMA16816(acc[mf][2*np+1], al[mf][0],al[mf][1],al[mf][2],al[mf][3], p2,p3);
                }
            }
        }
        __syncthreads();
    }

    // -------- fused epilogue: bias + residual -> LN -> write --------
    float* rsum  = (float*)smem;            // [4][128]
    float* rsq   = (float*)smem + 512;      // [4][128]
    float* smean = (float*)smem + 1024;     // [128]
    float* sinv  = (float*)smem + 1152;     // [128]

    float ps[4][2] = {}, pq[4][2] = {};
    const int rb = warpM * 64 + (lane >> 2);
    #pragma unroll
    for (int nf = 0; nf < 8; nf++) {
        const int c = warpN * 64 + nf * 8 + (lane & 3) * 2;
        float2 bb = *(const float2*)(bias + c);
        #pragma unroll
        for (int mf = 0; mf < 4; mf++) {
            const int gr0 = m0 + rb + mf * 16;
            float2 x0 = *(const float2*)(Xres + (size_t)gr0 * 256 + c);
            float2 x1 = *(const float2*)(Xres + (size_t)(gr0 + 8) * 256 + c);
            float v0 = acc[mf][nf][0] + bb.x + x0.x;
            float v1 = acc[mf][nf][1] + bb.y + x0.y;
            float v2 = acc[mf][nf][2] + bb.x + x1.x;
            float v3 = acc[mf][nf][3] + bb.y + x1.y;
            acc[mf][nf][0] = v0; acc[mf][nf][1] = v1;
            acc[mf][nf][2] = v2; acc[mf][nf][3] = v3;
            ps[mf][0] += v0 + v1; pq[mf][0] += v0*v0 + v1*v1;
            ps[mf][1] += v2 + v3; pq[mf][1] += v2*v2 + v3*v3;
        }
    }
    #pragma unroll
    for (int mf = 0; mf < 4; mf++)
        #pragma unroll
        for (int hh = 0; hh < 2; hh++) {
            float s = ps[mf][hh], q = pq[mf][hh];
            s += __shfl_xor_sync(0xffffffffu, s, 1);
            s += __shfl_xor_sync(0xffffffffu, s, 2);
            q += __shfl_xor_sync(0xffffffffu, q, 1);
            q += __shfl_xor_sync(0xffffffffu, q, 2);
            if ((lane & 3) == 0) {
                int lr = warpM * 64 + mf * 16 + (lane >> 2) + hh * 8;
                rsum[warpN * 128 + lr] = s;
                rsq [warpN * 128 + lr] = q;
            }
        }
    __syncthreads();
    if (tid < 128) {
        float s = rsum[tid] + rsum[128 + tid] + rsum[256 + tid] + rsum[384 + tid];
        float q = rsq [tid] + rsq [128 + tid] + rsq [256 + tid] + rsq [384 + tid];
        float mean = s * (1.0f / 256.0f);
        float var  = q * (1.0f / 256.0f) - mean * mean;
        smean[tid] = mean;
        sinv[tid]  = rsqrtf(var + 1e-5f);
    }
    __syncthreads();

    #pragma unroll
    for (int nf = 0; nf < 8; nf++) {
        const int c = warpN * 64 + nf * 8 + (lane & 3) * 2;
        float2 lw = *(const float2*)(lnw + c);
        float2 lb = *(const float2*)(lnb + c);
        #pragma unroll
        for (int mf = 0; mf < 4; mf++) {
            const int lr0 = rb + mf * 16;
            const int gr0 = m0 + lr0;
            float m0v = smean[lr0],     i0v = sinv[lr0];
            float m1v = smean[lr0 + 8], i1v = sinv[lr0 + 8];
            float o0 = (acc[mf][nf][0] - m0v) * i0v * lw.x + lb.x;
            float o1 = (acc[mf][nf][1] - m0v) * i0v * lw.y + lb.y;
            float o2 = (acc[mf][nf][2] - m1v) * i1v * lw.x + lb.x;
            float o3 = (acc[mf][nf][3] - m1v) * i1v * lw.y + lb.y;
            *(float2*)(Out + (size_t)gr0 * 256 + c) = make_float2(o0, o1);
            *(float2*)(Out + (size_t)(gr0 + 8) * 256 + c) = make_float2(o2, o3);
        }
    }
}

// ---------------- embed ----------------
__global__ void embed_kernel(const float* __restrict__ mi, const int* __restrict__ sse,
                             const float* __restrict__ w_in, const float* __restrict__ b_in,
                             float* __restrict__ x)
{
    size_t gid = (size_t)blockIdx.x * 256 + threadIdx.x;
    int d   = (int)(gid & 255);
    int tok = (int)(gid >> 8);
    int r   = tok % SQ_S;
    int seq = tok / SQ_S;
    int s   = seq & (SS - 1);
    int t   = seq >> 8;
    float val;
    if (r == 0) {
        val = 1e-5f;
    } else {
        int n = sse[2 * s] + (r - 1);
        const float* mp = mi + ((size_t)n * TT + t) * 2;
        float z = mp[0] * w_in[d * 2 + 0] + mp[1] * w_in[d * 2 + 1] + b_in[d];
        val = 0.5f * z * (1.0f + erff(z * 0.70710678118654752f));
    }
    x[gid] = val;
}

// ---------------- attention ----------------
__global__ void attn_kernel(const float* __restrict__ qkv, float* __restrict__ out, int Sq)
{
    const int seq  = blockIdx.x;
    const int head = blockIdx.y;
    const int tid  = threadIdx.x;
    const int lane = tid & 31;
    const int w    = tid >> 5;

    __shared__ float Ks[64][33];
    __shared__ float Vs[64][33];
    __shared__ float qs[4][33];
    __shared__ float ps[4][64];

    const float* base = qkv + (size_t)seq * Sq * (3 * DIMD) + head * HD;

    for (int idx = tid; idx < Sq * HD; idx += 128) {
        int rr = idx >> 5, dd = idx & 31;
        Ks[rr][dd] = base[(size_t)rr * (3 * DIMD) + DIMD + dd];
        Vs[rr][dd] = base[(size_t)rr * (3 * DIMD) + 2 * DIMD + dd];
    }
    __syncthreads();

    const float scale = 0.17677669529663689f;

    for (int i = w; i < Sq; i += 4) {
        qs[w][lane] = base[(size_t)i * (3 * DIMD) + lane];
        __syncwarp();
        float sc0 = -1e30f, sc1 = -1e30f;
        if (lane < Sq) {
            float sacc = 0.f;
            #pragma unroll
            for (int dd = 0; dd < HD; dd++) sacc += qs[w][dd] * Ks[lane][dd];
            sc0 = sacc * scale;
        }
        int j1 = lane + 32;
        if (j1 < Sq) {
            float sacc = 0.f;
            #pragma unroll
            for (int dd = 0; dd < HD; dd++) sacc += qs[w][dd] * Ks[j1][dd];
            sc1 = sacc * scale;
        }
        float mx = fmaxf(sc0, sc1);
        #pragma unroll
        for (int o = 16; o; o >>= 1) mx = fmaxf(mx, __shfl_xor_sync(0xffffffffu, mx, o));
        float e0 = (lane < Sq) ? expf(sc0 - mx) : 0.f;
        float e1 = (j1 < Sq) ? expf(sc1 - mx) : 0.f;
        float se = e0 + e1;
        #pragma unroll
        for (int o = 16; o; o >>= 1) se += __shfl_xor_sync(0xffffffffu, se, o);
        float inv = 1.f / se;
        if (lane < Sq) ps[w][lane] = e0 * inv;
        if (j1 < Sq)   ps[w][j1]   = e1 * inv;
        __syncwarp();
        float acc = 0.f;
        for (int j = 0; j < Sq; j++) acc += ps[w][j] * Vs[j][lane];
        out[((size_t)seq * Sq + i) * DIMD + head * HD + lane] = acc;
        __syncwarp();
    }
}

// ---------------- cls extraction ----------------
__global__ void extract_cls_kernel(const float* __restrict__ x, float* __restrict__ tx)
{
    size_t gid = (size_t)blockIdx.x * 256 + threadIdx.x;
    int d   = (int)(gid & 255);
    int tok = (int)(gid >> 8);
    int t = tok & (TT - 1);
    int s = tok >> 6;
    tx[gid] = x[(((size_t)t * SS + s) * SQ_S) * DIMD + d];
}

// ---------------- host orchestration ----------------
struct LayerW {
    const float *qkvb, *ob, *l1b, *l2b, *ln1w, *ln1b, *ln2w, *ln2b;
    const __nv_bfloat16 *qkvw_hi, *qkvw_lo, *ow_hi, *ow_lo, *l1w_hi, *l1w_lo, *l2w_hi, *l2w_lo;
};

static inline void launch_gemm(const float* A, const __nv_bfloat16* bh, const __nv_bfloat16* bl,
                               const float* bias, float* C, int M, int N, int K, int relu)
{
    dim3 grid(N / 128, M / 128);
    gemm_mma<<<grid, 256, GSMEM>>>(A, bh, bl, bias, C, M, N, K, relu);
}
static inline void launch_gemm_ln(const float* A, const __nv_bfloat16* bh, const __nv_bfloat16* bl,
                                  const float* bias, const float* X, const float* lnw,
                                  const float* lnb, float* Out, int M, int K)
{
    gemm_mma_ln<<<M / 128, 256, L_SMEM>>>(A, bh, bl, bias, X, lnw, lnb, Out, M, K);
}

static void run_layer(float* x, float* qkv, float* attnb, float* h,
                      const LayerW& L, int nseq, int Sq, float* final_out)
{
    const int ntok = nseq * Sq;
    launch_gemm(x, L.qkvw_hi, L.qkvw_lo, L.qkvb, qkv, ntok, 3 * DIMD, DIMD, 0);
    attn_kernel<<<dim3(nseq, HEADS), 128>>>(qkv, attnb, Sq);
    launch_gemm_ln(attnb, L.ow_hi, L.ow_lo, L.ob, x, L.ln1w, L.ln1b, x, ntok, DIMD);
    launch_gemm(x, L.l1w_hi, L.l1w_lo, L.l1b, h, ntok, DFF, DIMD, 1);
    launch_gemm_ln(h, L.l2w_hi, L.l2w_lo, L.l2b, x, L.ln2w, L.ln2b,
                   final_out ? final_out : x, ntok, DFF);
}

static LayerW make_layer(const float* const* p, int l, const __nv_bfloat16* whi,
                         const __nv_bfloat16* wlo, int enc)
{
    LayerW L;
    L.qkvb = p[1]  + (size_t)l * 3 * DIMD;
    L.ob   = p[3]  + (size_t)l * DIMD;
    L.l1b  = p[5]  + (size_t)l * DFF;
    L.l2b  = p[7]  + (size_t)l * DIMD;
    L.ln1w = p[8]  + (size_t)l * DIMD;
    L.ln1b = p[9]  + (size_t)l * DIMD;
    L.ln2w = p[10] + (size_t)l * DIMD;
    L.ln2b = p[11] + (size_t)l * DIMD;
    size_t eb = (size_t)enc * W_ENC;
    L.qkvw_hi = whi + eb + (size_t)l * 3 * DIMD * DIMD;
    L.qkvw_lo = wlo + eb + (size_t)l * 3 * DIMD * DIMD;
    L.ow_hi   = whi + eb + W_QKV + (size_t)l * DIMD * DIMD;
    L.ow_lo   = wlo + eb + W_QKV + (size_t)l * DIMD * DIMD;
    L.l1w_hi  = whi + eb + W_QKV + W_O + (size_t)l * DFF * DIMD;
    L.l1w_lo  = wlo + eb + W_QKV + W_O + (size_t)l * DFF * DIMD;
    L.l2w_hi  = whi + eb + W_QKV + W_O + W_L1 + (size_t)l * DIMD * DFF;
    L.l2w_lo  = wlo + eb + W_QKV + W_O + W_L1 + (size_t)l * DIMD * DFF;
    return L;
}

extern "C" void kernel_launch(void* const* d_in, const int* in_sizes, int n_in,
                              void* d_out, int out_size)
{
    const float* moveinfo = (const float*)d_in[0];
    const int*   sse      = (const int*)  d_in[1];
    const float* w_in     = (const float*)d_in[2];
    const float* b_in     = (const float*)d_in[3];
    const float* sp[12];
    const float* tp[12];
    for (int i = 0; i < 12; i++) sp[i] = (const float*)d_in[4 + i];
    for (int i = 0; i < 12; i++) tp[i] = (const float*)d_in[16 + i];

    float *x, *qkv, *attnb, *tmp, *h;
    __nv_bfloat16 *whi, *wlo;
    cudaGetSymbolAddress((void**)&x,     g_x);
    cudaGetSymbolAddress((void**)&qkv,   g_qkv);
    cudaGetSymbolAddress((void**)&attnb, g_attn);
    cudaGetSymbolAddress((void**)&tmp,   g_tmp);
    cudaGetSymbolAddress((void**)&h,     g_h);
    cudaGetSymbolAddress((void**)&whi,   g_whi);
    cudaGetSymbolAddress((void**)&wlo,   g_wlo);

    cudaFuncSetAttribute(gemm_mma, cudaFuncAttributeMaxDynamicSharedMemorySize, GSMEM);
    cudaFuncSetAttribute(gemm_mma_ln, cudaFuncAttributeMaxDynamicSharedMemorySize, L_SMEM);

    // 0) weight splits: 4 launches (launches #0-#3)
    split2_kernel<<<dim3((W_QKV + 255) / 256, 2), 256>>>(
        sp[0], whi, wlo, W_QKV,
        sp[2], whi + W_QKV, wlo + W_QKV, W_O);
    split2_kernel<<<dim3((W_L1 + 255) / 256, 2), 256>>>(
        sp[4], whi + W_QKV + W_O, wlo + W_QKV + W_O, W_L1,
        sp[6], whi + W_QKV + W_O + W_L1, wlo + W_QKV + W_O + W_L1, W_L2);
    split2_kernel<<<dim3((W_QKV + 255) / 256, 2), 256>>>(
        tp[0], whi + W_ENC, wlo + W_ENC, W_QKV,
        tp[2], whi + W_ENC + W_QKV, wlo + W_ENC + W_QKV, W_O);
    split2_kernel<<<dim3((W_L1 + 255) / 256, 2), 256>>>(
        tp[4], whi + W_ENC + W_QKV + W_O, wlo + W_ENC + W_QKV + W_O, W_L1,
        tp[6], whi + W_ENC + W_QKV + W_O + W_L1, wlo + W_ENC + W_QKV + W_O + W_L1, W_L2);

    // 1) embed (#4)
    embed_kernel<<<NTOK_S, 256>>>(moveinfo, sse, w_in, b_in, x);

    // 2) spatial encoder — spatial L0 QKV gemm is launch #5 (profiled)
    for (int l = 0; l < DEPTH; l++) {
        LayerW L = make_layer(sp, l, whi, wlo, 0);
        run_layer(x, qkv, attnb, h, L, NSEQ_S, SQ_S, nullptr);
    }

    // 3) cls extraction -> temporal input in tmp
    extract_cls_kernel<<<NTOK_T, 256>>>(x, tmp);

    // 4) temporal encoder
    for (int l = 0; l < DEPTH; l++) {
        LayerW L = make_layer(tp, l, whi, wlo, 1);
        float* fo = (l == DEPTH - 1) ? (float*)d_out : nullptr;
        run_layer(tmp, qkv, attnb, h, L, NSEQ_T, SQ_T, fo);
    }
}

// round 5
// speedup vs baseline: 2.0632x; 1.0299x over previous
#include <cuda_runtime.h>
#include <cuda_bf16.h>
#include <cstdint>

// ---------------- problem constants ----------------
#define DIMD   256
#define HEADS  8
#define HD     32
#define DEPTH  2
#define DFF    128
#define TT     64
#define SS     256
#define LL     8
#define NSEQ_S (TT*SS)
#define SQ_S   (1+LL)
#define NTOK_S (NSEQ_S*SQ_S)    // 147456
#define NSEQ_T SS
#define SQ_T   TT
#define NTOK_T (NSEQ_T*SQ_T)    // 16384

#define W_QKV (DEPTH*3*DIMD*DIMD)
#define W_O   (DEPTH*DIMD*DIMD)
#define W_L1  (DEPTH*DFF*DIMD)
#define W_L2  (DEPTH*DIMD*DFF)
#define W_ENC (W_QKV+W_O+W_L1+W_L2)

// ---------------- static scratch ----------------
__device__ __align__(16) float g_x   [(size_t)NTOK_S * DIMD];
__device__ __align__(16) float g_qkv [(size_t)NTOK_S * 3 * DIMD];
__device__ __align__(16) float g_attn[(size_t)NTOK_S * DIMD];
__device__ __align__(16) float g_tmp [(size_t)NTOK_S * DIMD];
__device__ __align__(16) float g_h   [(size_t)NTOK_S * DFF];
__device__ __align__(16) __nv_bfloat16 g_whi[2 * W_ENC];
__device__ __align__(16) __nv_bfloat16 g_wlo[2 * W_ENC];

__device__ __forceinline__ uint32_t smem_u32(const void* p) {
    uint32_t a;
    asm("{ .reg .u64 t; cvta.to.shared.u64 t, %1; cvt.u32.u64 %0, t; }" : "=r"(a) : "l"(p));
    return a;
}
__device__ __forceinline__ uint32_t pack_bf2(float x, float y) {
    __nv_bfloat162 t = __floats2bfloat162_rn(x, y);
    return *reinterpret_cast<uint32_t*>(&t);
}

#define LDSM4(R0,R1,R2,R3,ADDR) \
    asm volatile("ldmatrix.sync.aligned.m8n8.x4.shared.b16 {%0,%1,%2,%3}, [%4];" \
                 : "=r"(R0),"=r"(R1),"=r"(R2),"=r"(R3) : "r"(ADDR))

#define MMA16816(C, A0,A1,A2,A3, B0,B1) \
    asm volatile("mma.sync.aligned.m16n8k16.row.col.f32.bf16.bf16.f32 " \
                 "{%0,%1,%2,%3}, {%4,%5,%6,%7}, {%8,%9}, {%0,%1,%2,%3};" \
                 : "+f"((C)[0]),"+f"((C)[1]),"+f"((C)[2]),"+f"((C)[3]) \
                 : "r"(A0),"r"(A1),"r"(A2),"r"(A3), "r"(B0),"r"(B1))

#define CP_ASYNC16(DST, SRC) \
    asm volatile("cp.async.ca.shared.global [%0], [%1], 16;" :: "r"(DST), "l"(SRC))
#define CP_COMMIT()  asm volatile("cp.async.commit_group;" ::: "memory")
#define CP_WAIT1()   asm volatile("cp.async.wait_group 1;" ::: "memory")

// ---------------- weight split (two tensors per launch) ----------------
__global__ void split2_kernel(const float* __restrict__ s0, __nv_bfloat16* __restrict__ h0,
                              __nv_bfloat16* __restrict__ l0, int n0,
                              const float* __restrict__ s1, __nv_bfloat16* __restrict__ h1,
                              __nv_bfloat16* __restrict__ l1, int n1)
{
    const float* s = blockIdx.y ? s1 : s0;
    __nv_bfloat16* hh = blockIdx.y ? h1 : h0;
    __nv_bfloat16* ll = blockIdx.y ? l1 : l0;
    int n = blockIdx.y ? n1 : n0;
    int i = blockIdx.x * 256 + threadIdx.x;
    if (i < n) {
        float v = s[i];
        __nv_bfloat16 h = __float2bfloat16(v);
        hh[i] = h;
        ll[i] = __float2bfloat16(v - __bfloat162float(h));
    }
}

// ---------------- shared tile/pipe constants ----------------
#define APITCH 80
#define PARTB  10240
#define BOFF   20480
#define STAGEB 40960
#define GSMEM  (2*STAGEB)

#define L_PA   10240
#define L_BO   20480
#define L_PB   20480
#define L_STG  61440
#define L_SMEM (2*L_STG)

// A-operand load+split helpers (16 fp32 per thread per chunk)
#define LOAD_A16(AF, PTR) do { \
    const float4* _ap = (const float4*)(PTR); \
    float4 _t0 = _ap[0], _t1 = _ap[1], _t2 = _ap[2], _t3 = _ap[3]; \
    AF[0]=_t0.x; AF[1]=_t0.y; AF[2]=_t0.z; AF[3]=_t0.w; \
    AF[4]=_t1.x; AF[5]=_t1.y; AF[6]=_t1.z; AF[7]=_t1.w; \
    AF[8]=_t2.x; AF[9]=_t2.y; AF[10]=_t2.z; AF[11]=_t2.w; \
    AF[12]=_t3.x; AF[13]=_t3.y; AF[14]=_t3.z; AF[15]=_t3.w; \
} while (0)

#define STS_A_SPLIT(AF, A0, LOFF) do { \
    uint32_t _h[8], _l[8]; \
    _Pragma("unroll") \
    for (int _j = 0; _j < 8; _j++) { \
        float _v0 = AF[2*_j], _v1 = AF[2*_j+1]; \
        __nv_bfloat16 _h0 = __float2bfloat16(_v0); \
        __nv_bfloat16 _h1 = __float2bfloat16(_v1); \
        _h[_j] = ((uint32_t)__bfloat16_as_ushort(_h1) << 16) | __bfloat16_as_ushort(_h0); \
        _l[_j] = pack_bf2(_v0 - __bfloat162float(_h0), _v1 - __bfloat162float(_h1)); \
    } \
    asm volatile("st.shared.v4.b32 [%0], {%1,%2,%3,%4};" :: "r"(A0),          "r"(_h[0]),"r"(_h[1]),"r"(_h[2]),"r"(_h[3]) : "memory"); \
    asm volatile("st.shared.v4.b32 [%0], {%1,%2,%3,%4};" :: "r"(A0+16),       "r"(_h[4]),"r"(_h[5]),"r"(_h[6]),"r"(_h[7]) : "memory"); \
    asm volatile("st.shared.v4.b32 [%0], {%1,%2,%3,%4};" :: "r"(A0+(LOFF)),   "r"(_l[0]),"r"(_l[1]),"r"(_l[2]),"r"(_l[3]) : "memory"); \
    asm volatile("st.shared.v4.b32 [%0], {%1,%2,%3,%4};" :: "r"(A0+(LOFF)+16),"r"(_l[4]),"r"(_l[5]),"r"(_l[6]),"r"(_l[7]) : "memory"); \
} while (0)

// ========================================================================
// gemm_mma: C[M,N] = act(A @ W^T + bias).  CTA 128x128, BK=32, 8 warps 2x4.
// Used for FFN1 (N=128, relu).
// ========================================================================
__global__ void __launch_bounds__(256) gemm_mma(
    const float* __restrict__ A,
    const __nv_bfloat16* __restrict__ Bhi,
    const __nv_bfloat16* __restrict__ Blo,
    const float* __restrict__ bias,
    float* __restrict__ C,
    int M, int N, int K, int relu)
{
    extern __shared__ __align__(128) char smem[];
    const int tid  = threadIdx.x;
    const int lane = tid & 31;
    const int wid  = tid >> 5;
    const int warpM = wid >> 2;
    const int warpN = wid & 3;
    const int m0 = blockIdx.y * 128;
    const int n0 = blockIdx.x * 128;
    const uint32_t sb = smem_u32(smem);

    const int lrow = tid >> 1;
    const int lhalf = tid & 1;
    const float*         aptr = A   + (size_t)(m0 + lrow) * K + lhalf * 16;
    const __nv_bfloat16* bhp  = Bhi + (size_t)(n0 + lrow) * K + lhalf * 16;
    const __nv_bfloat16* blp  = Blo + (size_t)(n0 + lrow) * K + lhalf * 16;
    const uint32_t sts_off = (uint32_t)(lrow * APITCH + lhalf * 32);

    const int nch = K >> 5;

    float acc[4][4][4];
    #pragma unroll
    for (int i = 0; i < 4; i++)
        #pragma unroll
        for (int j = 0; j < 4; j++)
            #pragma unroll
            for (int q = 0; q < 4; q++) acc[i][j][q] = 0.f;

    float af[16];
    uint4 bhv[2], blv[2];
    {
        LOAD_A16(af, aptr);
        const uint4* bp = (const uint4*)bhp;
        bhv[0] = bp[0]; bhv[1] = bp[1];
        const uint4* lp = (const uint4*)blp;
        blv[0] = lp[0]; blv[1] = lp[1];
    }

    for (int c = 0; c < nch; c++) {
        {
            const uint32_t stage = sb + (uint32_t)(c & 1) * STAGEB;
            STS_A_SPLIT(af, stage + sts_off, PARTB);
            uint32_t b0 = stage + BOFF + sts_off;
            asm volatile("st.shared.v4.b32 [%0], {%1,%2,%3,%4};" :: "r"(b0),      "r"(bhv[0].x),"r"(bhv[0].y),"r"(bhv[0].z),"r"(bhv[0].w) : "memory");
            asm volatile("st.shared.v4.b32 [%0], {%1,%2,%3,%4};" :: "r"(b0+16),   "r"(bhv[1].x),"r"(bhv[1].y),"r"(bhv[1].z),"r"(bhv[1].w) : "memory");
            asm volatile("st.shared.v4.b32 [%0], {%1,%2,%3,%4};" :: "r"(b0+PARTB),"r"(blv[0].x),"r"(blv[0].y),"r"(blv[0].z),"r"(blv[0].w) : "memory");
            asm volatile("st.shared.v4.b32 [%0], {%1,%2,%3,%4};" :: "r"(b0+PARTB+16),"r"(blv[1].x),"r"(blv[1].y),"r"(blv[1].z),"r"(blv[1].w) : "memory");
        }
        __syncthreads();

        if (c + 1 < nch) {
            LOAD_A16(af, aptr + (c + 1) * 32);
            const uint4* bp = (const uint4*)(bhp + (c + 1) * 32);
            bhv[0] = bp[0]; bhv[1] = bp[1];
            const uint4* lp = (const uint4*)(blp + (c + 1) * 32);
            blv[0] = lp[0]; blv[1] = lp[1];
        }

        {
            const uint32_t stage = sb + (uint32_t)(c & 1) * STAGEB;
            #pragma unroll
            for (int ks = 0; ks < 2; ks++) {
                uint32_t ah[4][4], al[4][4];
                {
                    const int arow = warpM * 64 + (lane & 15);
                    const uint32_t abase = stage + (uint32_t)(ks * 32 + ((lane >> 4) & 1) * 16);
                    #pragma unroll
                    for (int mf = 0; mf < 4; mf++) {
                        uint32_t ad = abase + (uint32_t)((arow + mf * 16) * APITCH);
                        LDSM4(ah[mf][0], ah[mf][1], ah[mf][2], ah[mf][3], ad);
                        LDSM4(al[mf][0], al[mf][1], al[mf][2], al[mf][3], ad + PARTB);
                    }
                }
                uint32_t bh[4][2], bl[4][2];
                {
                    const int nrow = warpN * 32 + ((lane >> 4) & 1) * 8 + (lane & 7);
                    const uint32_t bbase = stage + BOFF + (uint32_t)(ks * 32 + ((lane >> 3) & 1) * 16);
                    #pragma unroll
                    for (int np = 0; np < 2; np++) {
                        uint32_t bd = bbase + (uint32_t)((nrow + np * 16) * APITCH);
                        LDSM4(bh[2*np][0], bh[2*np][1], bh[2*np+1][0], bh[2*np+1][1], bd);
                        LDSM4(bl[2*np][0], bl[2*np][1], bl[2*np+1][0], bl[2*np+1][1], bd + PARTB);
                    }
                }
                #pragma unroll
                for (int mf = 0; mf < 4; mf++)
                    #pragma unroll
                    for (int nf = 0; nf < 4; nf++) {
                        MMA16816(acc[mf][nf], ah[mf][0],ah[mf][1],ah[mf][2],ah[mf][3], bh[nf][0],bh[nf][1]);
                        MMA16816(acc[mf][nf], ah[mf][0],ah[mf][1],ah[mf][2],ah[mf][3], bl[nf][0],bl[nf][1]);
                        MMA16816(acc[mf][nf], al[mf][0],al[mf][1],al[mf][2],al[mf][3], bh[nf][0],bh[nf][1]);
                    }
            }
        }
        __syncthreads();
    }

    #pragma unroll
    for (int nf = 0; nf < 4; nf++) {
        const int col = n0 + warpN * 32 + nf * 8 + (lane & 3) * 2;
        const float b0 = bias[col], b1 = bias[col + 1];
        #pragma unroll
        for (int mf = 0; mf < 4; mf++) {
            const int r0 = m0 + warpM * 64 + mf * 16 + (lane >> 2);
            float v0 = acc[mf][nf][0] + b0;
            float v1 = acc[mf][nf][1] + b1;
            float v2 = acc[mf][nf][2] + b0;
            float v3 = acc[mf][nf][3] + b1;
            if (relu) {
                v0 = fmaxf(v0, 0.f); v1 = fmaxf(v1, 0.f);
                v2 = fmaxf(v2, 0.f); v3 = fmaxf(v3, 0.f);
            }
            *(float2*)(C + (size_t)r0 * N + col) = make_float2(v0, v1);
            *(float2*)(C + (size_t)(r0 + 8) * N + col) = make_float2(v2, v3);
        }
    }
}

// ========================================================================
// gemm_mma_wide: C[:, n0:n0+256] = A @ W^T + bias.  CTA 128x256, BK=32.
// B via cp.async. Used for QKV (N=768 row stride, 3 column tiles).
// ========================================================================
__global__ void __launch_bounds__(256) gemm_mma_wide(
    const float* __restrict__ A,
    const __nv_bfloat16* __restrict__ Bhi,
    const __nv_bfloat16* __restrict__ Blo,
    const float* __restrict__ bias,
    float* __restrict__ C,
    int M, int N, int K)
{
    extern __shared__ __align__(128) char smem[];
    const int tid  = threadIdx.x;
    const int lane = tid & 31;
    const int wid  = tid >> 5;
    const int warpM = wid >> 2;
    const int warpN = wid & 3;
    const int m0 = blockIdx.x * 128;
    const int n0 = blockIdx.y * 256;
    const uint32_t sb = smem_u32(smem);

    const int lrow = tid >> 1;
    const int lhalf = tid & 1;
    const float* aptr = A + (size_t)(m0 + lrow) * K + lhalf * 16;
    const uint32_t a_sts = (uint32_t)(lrow * APITCH + lhalf * 32);
    const char* bh_row = (const char*)(Bhi + (size_t)(n0 + tid) * K);
    const char* bl_row = (const char*)(Blo + (size_t)(n0 + tid) * K);
    const uint32_t b_sts = (uint32_t)(tid * APITCH);

    const int nch = K >> 5;

    float acc[4][8][4];
    #pragma unroll
    for (int i = 0; i < 4; i++)
        #pragma unroll
        for (int j = 0; j < 8; j++)
            #pragma unroll
            for (int q = 0; q < 4; q++) acc[i][j][q] = 0.f;

    float af[16];
    {
        LOAD_A16(af, aptr);
        uint32_t bd = sb + L_BO + b_sts;
        #pragma unroll
        for (int j = 0; j < 4; j++) {
            CP_ASYNC16(bd + j*16,        bh_row + j*16);
            CP_ASYNC16(bd + L_PB + j*16, bl_row + j*16);
        }
        CP_COMMIT();
    }

    for (int c = 0; c < nch; c++) {
        const uint32_t stage = sb + (uint32_t)(c & 1) * L_STG;
        STS_A_SPLIT(af, stage + a_sts, L_PA);
        if (c + 1 < nch) {
            uint32_t bd = sb + (uint32_t)((c + 1) & 1) * L_STG + L_BO + b_sts;
            const char* sh = bh_row + (size_t)(c + 1) * 64;
            const char* sl = bl_row + (size_t)(c + 1) * 64;
            #pragma unroll
            for (int j = 0; j < 4; j++) {
                CP_ASYNC16(bd + j*16,        sh + j*16);
                CP_ASYNC16(bd + L_PB + j*16, sl + j*16);
            }
        }
        CP_COMMIT();
        CP_WAIT1();
        __syncthreads();

        if (c + 1 < nch) LOAD_A16(af, aptr + (c + 1) * 32);

        #pragma unroll
        for (int ks = 0; ks < 2; ks++) {
            uint32_t ah[4][4], al[4][4];
            {
                const int arow = warpM * 64 + (lane & 15);
                const uint32_t abase = stage + (uint32_t)(ks * 32 + ((lane >> 4) & 1) * 16);
                #pragma unroll
                for (int mf = 0; mf < 4; mf++) {
                    uint32_t ad = abase + (uint32_t)((arow + mf * 16) * APITCH);
                    LDSM4(ah[mf][0], ah[mf][1], ah[mf][2], ah[mf][3], ad);
                    LDSM4(al[mf][0], al[mf][1], al[mf][2], al[mf][3], ad + L_PA);
                }
            }
            #pragma unroll
            for (int np = 0; np < 4; np++) {
                const int nrow = warpN * 64 + np * 16 + ((lane >> 4) & 1) * 8 + (lane & 7);
                const uint32_t bd = stage + L_BO + (uint32_t)(ks * 32 + ((lane >> 3) & 1) * 16)
                                  + (uint32_t)(nrow * APITCH);
                uint32_t p0, p1, p2, p3, q0, q1, q2, q3;
                LDSM4(p0, p1, p2, p3, bd);
                LDSM4(q0, q1, q2, q3, bd + L_PB);
                #pragma unroll
                for (int mf = 0; mf < 4; mf++) {
                    MMA16816(acc[mf][2*np],   ah[mf][0],ah[mf][1],ah[mf][2],ah[mf][3], p0,p1);
                    MMA16816(acc[mf][2*np],   ah[mf][0],ah[mf][1],ah[mf][2],ah[mf][3], q0,q1);
                    MMA16816(acc[mf][2*np],   al[mf][0],al[mf][1],al[mf][2],al[mf][3], p0,p1);
                    MMA16816(acc[mf][2*np+1], ah[mf][0],ah[mf][1],ah[mf][2],ah[mf][3], p2,p3);
                    MMA16816(acc[mf][2*np+1], ah[mf][0],ah[mf][1],ah[mf][2],ah[mf][3], q2,q3);
                    MMA16816(acc[mf][2*np+1], al[mf][0],al[mf][1],al[mf][2],al[mf][3], p2,p3);
                }
            }
        }
        __syncthreads();
    }

    #pragma unroll
    for (int nf = 0; nf < 8; nf++) {
        const int col = n0 + warpN * 64 + nf * 8 + (lane & 3) * 2;
        float2 bb = *(const float2*)(bias + col);
        #pragma unroll
        for (int mf = 0; mf < 4; mf++) {
            const int r0 = m0 + warpM * 64 + mf * 16 + (lane >> 2);
            *(float2*)(C + (size_t)r0 * N + col) =
                make_float2(acc[mf][nf][0] + bb.x, acc[mf][nf][1] + bb.y);
            *(float2*)(C + (size_t)(r0 + 8) * N + col) =
                make_float2(acc[mf][nf][2] + bb.x, acc[mf][nf][3] + bb.y);
        }
    }
}

// ========================================================================
// gemm_mma_ln: Out[M,256] = LN(Xres + (A @ W^T + bias)) * lnw + lnb
// ========================================================================
__global__ void __launch_bounds__(256) gemm_mma_ln(
    const float* __restrict__ A,
    const __nv_bfloat16* __restrict__ Bhi,
    const __nv_bfloat16* __restrict__ Blo,
    const float* __restrict__ bias,
    const float* __restrict__ Xres,
    const float* __restrict__ lnw,
    const float* __restrict__ lnb,
    float* __restrict__ Out,
    int M, int K)
{
    extern __shared__ __align__(128) char smem[];
    const int tid  = threadIdx.x;
    const int lane = tid & 31;
    const int wid  = tid >> 5;
    const int warpM = wid >> 2;
    const int warpN = wid & 3;
    const int m0 = blockIdx.x * 128;
    const uint32_t sb = smem_u32(smem);

    const int lrow = tid >> 1;
    const int lhalf = tid & 1;
    const float* aptr = A + (size_t)(m0 + lrow) * K + lhalf * 16;
    const uint32_t a_sts = (uint32_t)(lrow * APITCH + lhalf * 32);
    const char* bh_row = (const char*)(Bhi + (size_t)tid * K);
    const char* bl_row = (const char*)(Blo + (size_t)tid * K);
    const uint32_t b_sts = (uint32_t)(tid * APITCH);

    const int nch = K >> 5;

    float acc[4][8][4];
    #pragma unroll
    for (int i = 0; i < 4; i++)
        #pragma unroll
        for (int j = 0; j < 8; j++)
            #pragma unroll
            for (int q = 0; q < 4; q++) acc[i][j][q] = 0.f;

    float af[16];
    {
        LOAD_A16(af, aptr);
        uint32_t bd = sb + L_BO + b_sts;
        #pragma unroll
        for (int j = 0; j < 4; j++) {
            CP_ASYNC16(bd + j*16,        bh_row + j*16);
            CP_ASYNC16(bd + L_PB + j*16, bl_row + j*16);
        }
        CP_COMMIT();
    }

    for (int c = 0; c < nch; c++) {
        const uint32_t stage = sb + (uint32_t)(c & 1) * L_STG;
        STS_A_SPLIT(af, stage + a_sts, L_PA);
        if (c + 1 < nch) {
            uint32_t bd = sb + (uint32_t)((c + 1) & 1) * L_STG + L_BO + b_sts;
            const char* sh = bh_row + (size_t)(c + 1) * 64;
            const char* sl = bl_row + (size_t)(c + 1) * 64;
            #pragma unroll
            for (int j = 0; j < 4; j++) {
                CP_ASYNC16(bd + j*16,        sh + j*16);
                CP_ASYNC16(bd + L_PB + j*16, sl + j*16);
            }
        }
        CP_COMMIT();
        CP_WAIT1();
        __syncthreads();

        if (c + 1 < nch) LOAD_A16(af, aptr + (c + 1) * 32);

        #pragma unroll
        for (int ks = 0; ks < 2; ks++) {
            uint32_t ah[4][4], al[4][4];
            {
                const int arow = warpM * 64 + (lane & 15);
                const uint32_t abase = stage + (uint32_t)(ks * 32 + ((lane >> 4) & 1) * 16);
                #pragma unroll
                for (int mf = 0; mf < 4; mf++) {
                    uint32_t ad = abase + (uint32_t)((arow + mf * 16) * APITCH);
                    LDSM4(ah[mf][0], ah[mf][1], ah[mf][2], ah[mf][3], ad);
                    LDSM4(al[mf][0], al[mf][1], al[mf][2], al[mf][3], ad + L_PA);
                }
            }
            #pragma unroll
            for (int np = 0; np < 4; np++) {
                const int nrow = warpN * 64 + np * 16 + ((lane >> 4) & 1) * 8 + (lane & 7);
                const uint32_t bd = stage + L_BO + (uint32_t)(ks * 32 + ((lane >> 3) & 1) * 16)
                                  + (uint32_t)(nrow * APITCH);
                uint32_t p0, p1, p2, p3, q0, q1, q2, q3;
                LDSM4(p0, p1, p2, p3, bd);
                LDSM4(q0, q1, q2, q3, bd + L_PB);
                #pragma unroll
                for (int mf = 0; mf < 4; mf++) {
                    MMA16816(acc[mf][2*np],   ah[mf][0],ah[mf][1],ah[mf][2],ah[mf][3], p0,p1);
                    MMA16816(acc[mf][2*np],   ah[mf][0],ah[mf][1],ah[mf][2],ah[mf][3], q0,q1);
                    MMA16816(acc[mf][2*np],   al[mf][0],al[mf][1],al[mf][2],al[mf][3], p0,p1);
                    MMA16816(acc[mf][2*np+1], ah[mf][0],ah[mf][1],ah[mf][2],ah[mf][3], p2,p3);
                    MMA16816(acc[mf][2*np+1], ah[mf][0],ah[mf][1],ah[mf][2],ah[mf][3], q2,q3);
                    MMA16816(acc[mf][2*np+1], al[mf][0],al[mf][1],al[mf][2],al[mf][3], p2,p3);
                }
            }
        }
        __syncthreads();
    }

    float* rsum  = (float*)smem;
    float* rsq   = (float*)smem + 512;
    float* smean = (float*)smem + 1024;
    float* sinv  = (float*)smem + 1152;

    float ps[4][2] = {}, pq[4][2] = {};
    const int rb = warpM * 64 + (lane >> 2);
    #pragma unroll
    for (int nf = 0; nf < 8; nf++) {
        const int c = warpN * 64 + nf * 8 + (lane & 3) * 2;
        float2 bb = *(const float2*)(bias + c);
        #pragma unroll
        for (int mf = 0; mf < 4; mf++) {
            const int gr0 = m0 + rb + mf * 16;
            float2 x0 = *(const float2*)(Xres + (size_t)gr0 * 256 + c);
            float2 x1 = *(const float2*)(Xres + (size_t)(gr0 + 8) * 256 + c);
            float v0 = acc[mf][nf][0] + bb.x + x0.x;
            float v1 = acc[mf][nf][1] + bb.y + x0.y;
            float v2 = acc[mf][nf][2] + bb.x + x1.x;
            float v3 = acc[mf][nf][3] + bb.y + x1.y;
            acc[mf][nf][0] = v0; acc[mf][nf][1] = v1;
            acc[mf][nf][2] = v2; acc[mf][nf][3] = v3;
            ps[mf][0] += v0 + v1; pq[mf][0] += v0*v0 + v1*v1;
            ps[mf][1] += v2 + v3; pq[mf][1] += v2*v2 + v3*v3;
        }
    }
    #pragma unroll
    for (int mf = 0; mf < 4; mf++)
        #pragma unroll
        for (int hh = 0; hh < 2; hh++) {
            float s = ps[mf][hh], q = pq[mf][hh];
            s += __shfl_xor_sync(0xffffffffu, s, 1);
            s += __shfl_xor_sync(0xffffffffu, s, 2);
            q += __shfl_xor_sync(0xffffffffu, q, 1);
            q += __shfl_xor_sync(0xffffffffu, q, 2);
            if ((lane & 3) == 0) {
                int lr = warpM * 64 + mf * 16 + (lane >> 2) + hh * 8;
                rsum[warpN * 128 + lr] = s;
                rsq [warpN * 128 + lr] = q;
            }
        }
    __syncthreads();
    if (tid < 128) {
        float s = rsum[tid] + rsum[128 + tid] + rsum[256 + tid] + rsum[384 + tid];
        float q = rsq [tid] + rsq [128 + tid] + rsq [256 + tid] + rsq [384 + tid];
        float mean = s * (1.0f / 256.0f);
        float var  = q * (1.0f / 256.0f) - mean * mean;
        smean[tid] = mean;
        sinv[tid]  = rsqrtf(var + 1e-5f);
    }
    __syncthreads();

    #pragma unroll
    for (int nf = 0; nf < 8; nf++) {
        const int c = warpN * 64 + nf * 8 + (lane & 3) * 2;
        float2 lw = *(const float2*)(lnw + c);
        float2 lb = *(const float2*)(lnb + c);
        #pragma unroll
        for (int mf = 0; mf < 4; mf++) {
            const int lr0 = rb + mf * 16;
            const int gr0 = m0 + lr0;
            float m0v = smean[lr0],     i0v = sinv[lr0];
            float m1v = smean[lr0 + 8], i1v = sinv[lr0 + 8];
            float o0 = (acc[mf][nf][0] - m0v) * i0v * lw.x + lb.x;
            float o1 = (acc[mf][nf][1] - m0v) * i0v * lw.y + lb.y;
            float o2 = (acc[mf][nf][2] - m1v) * i1v * lw.x + lb.x;
            float o3 = (acc[mf][nf][3] - m1v) * i1v * lw.y + lb.y;
            *(float2*)(Out + (size_t)gr0 * 256 + c) = make_float2(o0, o1);
            *(float2*)(Out + (size_t)(gr0 + 8) * 256 + c) = make_float2(o2, o3);
        }
    }
}

// ---------------- embed ----------------
__global__ void embed_kernel(const float* __restrict__ mi, const int* __restrict__ sse,
                             const float* __restrict__ w_in, const float* __restrict__ b_in,
                             float* __restrict__ x)
{
    size_t gid = (size_t)blockIdx.x * 256 + threadIdx.x;
    int d   = (int)(gid & 255);
    int tok = (int)(gid >> 8);
    int r   = tok % SQ_S;
    int seq = tok / SQ_S;
    int s   = seq & (SS - 1);
    int t   = seq >> 8;
    float val;
    if (r == 0) {
        val = 1e-5f;
    } else {
        int n = sse[2 * s] + (r - 1);
        const float* mp = mi + ((size_t)n * TT + t) * 2;
        float z = mp[0] * w_in[d * 2 + 0] + mp[1] * w_in[d * 2 + 1] + b_in[d];
        val = 0.5f * z * (1.0f + erff(z * 0.70710678118654752f));
    }
    x[gid] = val;
}

// ---------------- spatial attention: 1 block/sequence, warp = head (Sq=9) ----------------
__global__ void __launch_bounds__(256) attn9_kernel(const float* __restrict__ qkv,
                                                    float* __restrict__ out)
{
    const int seq  = blockIdx.x;
    const int tid  = threadIdx.x;
    const int lane = tid & 31;
    const int w    = tid >> 5;     // head

    __shared__ float s[SQ_S * 768];      // 27648 B
    __shared__ float ps[8][16];

    const float4* src = (const float4*)(qkv + (size_t)seq * SQ_S * 768);
    #pragma unroll
    for (int i = 0; i < 7; i++) {
        int idx = tid + i * 256;         // 1728 float4s
        if (idx < SQ_S * 192)
            ((float4*)s)[idx] = src[idx];
    }
    __syncthreads();

    const float scale = 0.17677669529663689f;
    const int hc = w * HD;

    #pragma unroll
    for (int i = 0; i < SQ_S; i++) {
        float sc = -1e30f;
        if (lane < SQ_S) {
            float a = 0.f;
            const float* qrow = s + i * 768 + hc;
            const float* krow = s + lane * 768 + 256 + hc;
            #pragma unroll
            for (int d0 = 0; d0 < HD; d0++) {
                int d = (d0 + lane) & 31;       // rotate: conflict-free
                a += qrow[d] * krow[d];
            }
            sc = a * scale;
        }
        float mx = sc;
        #pragma unroll
        for (int o = 16; o; o >>= 1) mx = fmaxf(mx, __shfl_xor_sync(0xffffffffu, mx, o));
        float e = (lane < SQ_S) ? expf(sc - mx) : 0.f;
        float se = e;
        #pragma unroll
        for (int o = 16; o; o >>= 1) se += __shfl_xor_sync(0xffffffffu, se, o);
        if (lane < SQ_S) ps[w][lane] = e / se;
        __syncwarp();
        float acc = 0.f;
        #pragma unroll
        for (int j = 0; j < SQ_S; j++)
            acc += ps[w][j] * s[j * 768 + 512 + hc + lane];
        out[((size_t)seq * SQ_S + i) * DIMD + hc + lane] = acc;
        __syncwarp();
    }
}

// ---------------- temporal attention (Sq=64) ----------------
__global__ void attn_kernel(const float* __restrict__ qkv, float* __restrict__ out, int Sq)
{
    const int seq  = blockIdx.x;
    const int head = blockIdx.y;
    const int tid  = threadIdx.x;
    const int lane = tid & 31;
    const int w    = tid >> 5;

    __shared__ float Ks[64][33];
    __shared__ float Vs[64][33];
    __shared__ float qs[4][33];
    __shared__ float ps[4][64];

    const float* base = qkv + (size_t)seq * Sq * (3 * DIMD) + head * HD;

    for (int idx = tid; idx < Sq * HD; idx += 128) {
        int rr = idx >> 5, dd = idx & 31;
        Ks[rr][dd] = base[(size_t)rr * (3 * DIMD) + DIMD + dd];
        Vs[rr][dd] = base[(size_t)rr * (3 * DIMD) + 2 * DIMD + dd];
    }
    __syncthreads();

    const float scale = 0.17677669529663689f;

    for (int i = w; i < Sq; i += 4) {
        qs[w][lane] = base[(size_t)i * (3 * DIMD) + lane];
        __syncwarp();
        float sc0 = -1e30f, sc1 = -1e30f;
        if (lane < Sq) {
            float sacc = 0.f;
            #pragma unroll
            for (int dd = 0; dd < HD; dd++) sacc += qs[w][dd] * Ks[lane][dd];
            sc0 = sacc * scale;
        }
        int j1 = lane + 32;
        if (j1 < Sq) {
            float sacc = 0.f;
            #pragma unroll
            for (int dd = 0; dd < HD; dd++) sacc += qs[w][dd] * Ks[j1][dd];
            sc1 = sacc * scale;
        }
        float mx = fmaxf(sc0, sc1);
        #pragma unroll
        for (int o = 16; o; o >>= 1) mx = fmaxf(mx, __shfl_xor_sync(0xffffffffu, mx, o));
        float e0 = (lane < Sq) ? expf(sc0 - mx) : 0.f;
        float e1 = (j1 < Sq) ? expf(sc1 - mx) : 0.f;
        float se = e0 + e1;
        #pragma unroll
        for (int o = 16; o; o >>= 1) se += __shfl_xor_sync(0xffffffffu, se, o);
        float inv = 1.f / se;
        if (lane < Sq) ps[w][lane] = e0 * inv;
        if (j1 < Sq)   ps[w][j1]   = e1 * inv;
        __syncwarp();
        float acc = 0.f;
        for (int j = 0; j < Sq; j++) acc += ps[w][j] * Vs[j][lane];
        out[((size_t)seq * Sq + i) * DIMD + head * HD + lane] = acc;
        __syncwarp();
    }
}

// ---------------- cls extraction ----------------
__global__ void extract_cls_kernel(const float* __restrict__ x, float* __restrict__ tx)
{
    size_t gid = (size_t)blockIdx.x * 256 + threadIdx.x;
    int d   = (int)(gid & 255);
    int tok = (int)(gid >> 8);
    int t = tok & (TT - 1);
    int s = tok >> 6;
    tx[gid] = x[(((size_t)t * SS + s) * SQ_S) * DIMD + d];
}

// ---------------- host orchestration ----------------
struct LayerW {
    const float *qkvb, *ob, *l1b, *l2b, *ln1w, *ln1b, *ln2w, *ln2b;
    const __nv_bfloat16 *qkvw_hi, *qkvw_lo, *ow_hi, *ow_lo, *l1w_hi, *l1w_lo, *l2w_hi, *l2w_lo;
};

static void run_layer(float* x, float* qkv, float* attnb, float* h,
                      const LayerW& L, int nseq, int Sq, float* final_out)
{
    const int ntok = nseq * Sq;
    gemm_mma_wide<<<dim3(ntok / 128, 3), 256, L_SMEM>>>(
        x, L.qkvw_hi, L.qkvw_lo, L.qkvb, qkv, ntok, 3 * DIMD, DIMD);
    if (Sq == SQ_S)
        attn9_kernel<<<nseq, 256>>>(qkv, attnb);
    else
        attn_kernel<<<dim3(nseq, HEADS), 128>>>(qkv, attnb, Sq);
    gemm_mma_ln<<<ntok / 128, 256, L_SMEM>>>(
        attnb, L.ow_hi, L.ow_lo, L.ob, x, L.ln1w, L.ln1b, x, ntok, DIMD);
    gemm_mma<<<dim3(1, ntok / 128), 256, GSMEM>>>(
        x, L.l1w_hi, L.l1w_lo, L.l1b, h, ntok, DFF, DIMD, 1);
    gemm_mma_ln<<<ntok / 128, 256, L_SMEM>>>(
        h, L.l2w_hi, L.l2w_lo, L.l2b, x, L.ln2w, L.ln2b,
        final_out ? final_out : x, ntok, DFF);
}

static LayerW make_layer(const float* const* p, int l, const __nv_bfloat16* whi,
                         const __nv_bfloat16* wlo, int enc)
{
    LayerW L;
    L.qkvb = p[1]  + (size_t)l * 3 * DIMD;
    L.ob   = p[3]  + (size_t)l * DIMD;
    L.l1b  = p[5]  + (size_t)l * DFF;
    L.l2b  = p[7]  + (size_t)l * DIMD;
    L.ln1w = p[8]  + (size_t)l * DIMD;
    L.ln1b = p[9]  + (size_t)l * DIMD;
    L.ln2w = p[10] + (size_t)l * DIMD;
    L.ln2b = p[11] + (size_t)l * DIMD;
    size_t eb = (size_t)enc * W_ENC;
    L.qkvw_hi = whi + eb + (size_t)l * 3 * DIMD * DIMD;
    L.qkvw_lo = wlo + eb + (size_t)l * 3 * DIMD * DIMD;
    L.ow_hi   = whi + eb + W_QKV + (size_t)l * DIMD * DIMD;
    L.ow_lo   = wlo + eb + W_QKV + (size_t)l * DIMD * DIMD;
    L.l1w_hi  = whi + eb + W_QKV + W_O + (size_t)l * DFF * DIMD;
    L.l1w_lo  = wlo + eb + W_QKV + W_O + (size_t)l * DFF * DIMD;
    L.l2w_hi  = whi + eb + W_QKV + W_O + W_L1 + (size_t)l * DIMD * DFF;
    L.l2w_lo  = wlo + eb + W_QKV + W_O + W_L1 + (size_t)l * DIMD * DFF;
    return L;
}

extern "C" void kernel_launch(void* const* d_in, const int* in_sizes, int n_in,
                              void* d_out, int out_size)
{
    const float* moveinfo = (const float*)d_in[0];
    const int*   sse      = (const int*)  d_in[1];
    const float* w_in     = (const float*)d_in[2];
    const float* b_in     = (const float*)d_in[3];
    const float* sp[12];
    const float* tp[12];
    for (int i = 0; i < 12; i++) sp[i] = (const float*)d_in[4 + i];
    for (int i = 0; i < 12; i++) tp[i] = (const float*)d_in[16 + i];

    float *x, *qkv, *attnb, *tmp, *h;
    __nv_bfloat16 *whi, *wlo;
    cudaGetSymbolAddress((void**)&x,     g_x);
    cudaGetSymbolAddress((void**)&qkv,   g_qkv);
    cudaGetSymbolAddress((void**)&attnb, g_attn);
    cudaGetSymbolAddress((void**)&tmp,   g_tmp);
    cudaGetSymbolAddress((void**)&h,     g_h);
    cudaGetSymbolAddress((void**)&whi,   g_whi);
    cudaGetSymbolAddress((void**)&wlo,   g_wlo);

    cudaFuncSetAttribute(gemm_mma, cudaFuncAttributeMaxDynamicSharedMemorySize, GSMEM);
    cudaFuncSetAttribute(gemm_mma_wide, cudaFuncAttributeMaxDynamicSharedMemorySize, L_SMEM);
    cudaFuncSetAttribute(gemm_mma_ln, cudaFuncAttributeMaxDynamicSharedMemorySize, L_SMEM);

    split2_kernel<<<dim3((W_QKV + 255) / 256, 2), 256>>>(
        sp[0], whi, wlo, W_QKV,
        sp[2], whi + W_QKV, wlo + W_QKV, W_O);
    split2_kernel<<<dim3((W_L1 + 255) / 256, 2), 256>>>(
        sp[4], whi + W_QKV + W_O, wlo + W_QKV + W_O, W_L1,
        sp[6], whi + W_QKV + W_O + W_L1, wlo + W_QKV + W_O + W_L1, W_L2);
    split2_kernel<<<dim3((W_QKV + 255) / 256, 2), 256>>>(
        tp[0], whi + W_ENC, wlo + W_ENC, W_QKV,
        tp[2], whi + W_ENC + W_QKV, wlo + W_ENC + W_QKV, W_O);
    split2_kernel<<<dim3((W_L1 + 255) / 256, 2), 256>>>(
        tp[4], whi + W_ENC + W_QKV + W_O, wlo + W_ENC + W_QKV + W_O, W_L1,
        tp[6], whi + W_ENC + W_QKV + W_O + W_L1, wlo + W_ENC + W_QKV + W_O + W_L1, W_L2);

    embed_kernel<<<NTOK_S, 256>>>(moveinfo, sse, w_in, b_in, x);

    for (int l = 0; l < DEPTH; l++) {
        LayerW L = make_layer(sp, l, whi, wlo, 0);
        run_layer(x, qkv, attnb, h, L, NSEQ_S, SQ_S, nullptr);
    }

    extract_cls_kernel<<<NTOK_T, 256>>>(x, tmp);

    for (int l = 0; l < DEPTH; l++) {
        LayerW L = make_layer(tp, l, whi, wlo, 1);
        float* fo = (l == DEPTH - 1) ? (float*)d_out : nullptr;
        run_layer(tmp, qkv, attnb, h, L, NSEQ_T, SQ_T, fo);
    }
}